// round 1
// baseline (speedup 1.0000x reference)
#include <cuda_runtime.h>
#include <math.h>

// ---------------- problem constants ----------------
namespace {
constexpr int T_    = 2048;
constexpr int HID   = 2048;
constexpr int H_    = 32;
constexpr int HKV   = 2;
constexpr int DQK   = 64;
constexpr int DV    = 64;
constexpr int G_    = 2;       // = HKV
constexpr int HG    = 16;      // H / HKV
constexpr int BLK   = 32;
constexpr int NSEL  = 8;
constexpr int WINSZ = 256;
constexpr int NB    = 64;      // T / BLK
constexpr int OUTD  = 2400;    // H*(DQK+3) + HKV*(DQK+DV)
// offsets within a qkvw row
constexpr int OQ = 0;
constexpr int OK_ = 2048;      // H*DQK
constexpr int OV  = 2176;      // + HKV*DQK
constexpr int OW  = 2304;      // + HKV*DV
constexpr float SCALE = 0.125f;   // DQK^-0.5
constexpr float NEGI  = -1e30f;
}

// ---------------- scratch (device globals; allocation-free) ----------------
__device__ float g_qkvw[(size_t)T_ * OUTD];        // fused projection (rope applied in place)
__device__ float g_kcmp[NB * G_ * DQK];
__device__ float g_vcmp[NB * G_ * DV];
__device__ float g_ocmp[(size_t)T_ * H_ * DV];
__device__ float g_osel[(size_t)T_ * H_ * DV];
__device__ float g_owin[(size_t)T_ * H_ * DV];
__device__ float g_ocomb[(size_t)T_ * H_ * DV];
__device__ int   g_selidx[T_ * G_ * NSEL];

// ---------------- classic 128x128x8 SGEMM (fp32) ----------------
// A: [M,K] row-major, B: [K,N] row-major, C: [M,N] row-major.
// M, K multiples of 128/8; N guarded (N % 4 == 0 required).
__global__ void sgemm_kernel(const float* __restrict__ A, const float* __restrict__ B,
                             float* __restrict__ C, int M, int N, int K) {
    __shared__ float As[8][128];
    __shared__ float Bs[8][128];
    const int tid = threadIdx.x;          // 256 threads
    const int bx = blockIdx.x, by = blockIdx.y;
    const int tx = tid & 15, ty = tid >> 4;
    const int aRow  = tid >> 1;
    const int aCol4 = (tid & 1) << 2;
    const int bRow  = tid >> 5;
    const int bCol  = (tid & 31) << 2;
    const int cColBase = bx * 128;

    float acc[8][8];
#pragma unroll
    for (int i = 0; i < 8; i++)
#pragma unroll
        for (int j = 0; j < 8; j++) acc[i][j] = 0.f;
    float ar[8], br[8];

    for (int k0 = 0; k0 < K; k0 += 8) {
        float4 a4 = *reinterpret_cast<const float4*>(A + (size_t)(by * 128 + aRow) * K + k0 + aCol4);
        As[aCol4 + 0][aRow] = a4.x;
        As[aCol4 + 1][aRow] = a4.y;
        As[aCol4 + 2][aRow] = a4.z;
        As[aCol4 + 3][aRow] = a4.w;
        float4 b4 = make_float4(0.f, 0.f, 0.f, 0.f);
        int gc = cColBase + bCol;
        if (gc < N) b4 = *reinterpret_cast<const float4*>(B + (size_t)(k0 + bRow) * N + gc);
        *reinterpret_cast<float4*>(&Bs[bRow][bCol]) = b4;
        __syncthreads();
#pragma unroll
        for (int kk = 0; kk < 8; kk++) {
#pragma unroll
            for (int i = 0; i < 8; i++) ar[i] = As[kk][ty * 8 + i];
#pragma unroll
            for (int j = 0; j < 8; j++) br[j] = Bs[kk][tx * 8 + j];
#pragma unroll
            for (int i = 0; i < 8; i++)
#pragma unroll
                for (int j = 0; j < 8; j++) acc[i][j] += ar[i] * br[j];
        }
        __syncthreads();
    }
#pragma unroll
    for (int i = 0; i < 8; i++) {
        int row = by * 128 + ty * 8 + i;
#pragma unroll
        for (int j = 0; j < 8; j += 4) {
            int col = cColBase + tx * 8 + j;
            if (col < N) {
                *reinterpret_cast<float4*>(C + (size_t)row * N + col) =
                    make_float4(acc[i][j], acc[i][j + 1], acc[i][j + 2], acc[i][j + 3]);
            }
        }
    }
}

// ---------------- NeoX RoPE, in place on q and k slices ----------------
__global__ void rope_kernel(const float* __restrict__ cosp, const float* __restrict__ sinp) {
    int t = blockIdx.x;
    float* row = g_qkvw + (size_t)t * OUTD;
    for (int i = threadIdx.x; i < (H_ + HKV) * 32; i += blockDim.x) {
        int head = i >> 5, dp = i & 31;
        float* base = (head < H_) ? (row + OQ + head * DQK)
                                  : (row + OK_ + (head - H_) * DQK);
        float x1 = base[dp], x2 = base[dp + 32];
        float c1 = cosp[t * DQK + dp],      s1 = sinp[t * DQK + dp];
        float c2 = cosp[t * DQK + dp + 32], s2 = sinp[t * DQK + dp + 32];
        base[dp]      = x1 * c1 - x2 * s1;
        base[dp + 32] = x2 * c2 + x1 * s2;
    }
}

// ---------------- block mean-pool of (roped) K and V ----------------
__global__ void pool_kernel() {
    int idx = blockIdx.x * blockDim.x + threadIdx.x;
    if (idx >= NB * G_ * DQK) return;
    int nb = idx / (G_ * DQK);
    int g  = (idx / DQK) % G_;
    int d  = idx % DQK;
    float sk = 0.f, sv = 0.f;
    for (int i = 0; i < BLK; i++) {
        const float* r = g_qkvw + (size_t)(nb * BLK + i) * OUTD;
        sk += r[OK_ + g * DQK + d];
        sv += r[OV  + g * DV  + d];
    }
    g_kcmp[idx] = sk * (1.f / BLK);
    g_vcmp[idx] = sv * (1.f / BLK);
}

// ---------------- compressed branch + importance + top-k ----------------
// grid (T, G), 128 threads
__global__ void cmp_kernel() {
    int t = blockIdx.x, g = blockIdx.y;
    __shared__ float kc[NB][DQK];
    __shared__ float vc[NB][DV];
    __shared__ float qs[HG][DQK];
    __shared__ float p[HG][NB];
    __shared__ float imp[NB];
    const int tid = threadIdx.x;

    for (int i = tid; i < NB * DQK; i += 128) {
        int n = i >> 6, d = i & 63;
        kc[n][d] = g_kcmp[(n * G_ + g) * DQK + d];
        vc[n][d] = g_vcmp[(n * G_ + g) * DV + d];
    }
    for (int i = tid; i < HG * DQK; i += 128) {
        int hh = i >> 6, d = i & 63;
        qs[hh][d] = g_qkvw[(size_t)t * OUTD + OQ + (g * HG + hh) * DQK + d];
    }
    __syncthreads();

    const int nvis = (t + 1) >> 5;   // blocks fully in the past
    for (int i = tid; i < HG * NB; i += 128) {
        int hh = i >> 6, n = i & 63;
        float s = NEGI;
        if (n < nvis) {
            float acc = 0.f;
            for (int d = 0; d < DQK; d++) acc += qs[hh][d] * kc[n][d];
            s = acc * SCALE;
        }
        p[hh][n] = s;
    }
    __syncthreads();

    if (tid < HG) {
        if (nvis == 0) {
            for (int n = 0; n < NB; n++) p[tid][n] = 0.f;
        } else {
            float m = NEGI;
            for (int n = 0; n < NB; n++) m = fmaxf(m, p[tid][n]);
            float s = 0.f;
            for (int n = 0; n < NB; n++) { float e = expf(p[tid][n] - m); p[tid][n] = e; s += e; }
            float inv = 1.f / s;
            for (int n = 0; n < NB; n++) p[tid][n] *= inv;
        }
    }
    __syncthreads();

    const int cur = t >> 5;
    if (tid < NB) {
        float v = 0.f;
        for (int hh = 0; hh < HG; hh++) v += p[hh][tid];
        if (tid == 0)   v += 1e4f;
        if (tid == cur) v += 1e4f;
        if (tid > cur)  v = NEGI;
        imp[tid] = v;
    }
    __syncthreads();

    if (tid == 0) {
        for (int j = 0; j < NSEL; j++) {
            int am = 0; float mv = imp[0];
            for (int n = 1; n < NB; n++)
                if (imp[n] > mv) { mv = imp[n]; am = n; }   // strict > = lowest-index tie break
            g_selidx[(t * G_ + g) * NSEL + j] = am;
            imp[am] = -2e30f;
        }
    }
    __syncthreads();

    for (int i = tid; i < HG * DV; i += 128) {
        int hh = i >> 6, d = i & 63;
        float acc = 0.f;
        for (int n = 0; n < NB; n++) acc += p[hh][n] * vc[n][d];
        g_ocmp[((size_t)t * H_ + g * HG + hh) * DV + d] = acc;
    }
}

// ---------------- selection branch ----------------
// grid (T, G), 256 threads
__global__ void sel_kernel() {
    int t = blockIdx.x, g = blockIdx.y;
    __shared__ float qs[HG][DQK];
    __shared__ float kb[BLK][DQK];           // reused for V in pass 2
    __shared__ float p[HG][NSEL * BLK];
    __shared__ int sidx[NSEL];
    const int tid = threadIdx.x;

    if (tid < NSEL) sidx[tid] = g_selidx[(t * G_ + g) * NSEL + tid];
    for (int i = tid; i < HG * DQK; i += 256) {
        int hh = i >> 6, d = i & 63;
        qs[hh][d] = g_qkvw[(size_t)t * OUTD + OQ + (g * HG + hh) * DQK + d];
    }
    __syncthreads();

    for (int c = 0; c < NSEL; c++) {
        int n = sidx[c];
        for (int i = tid; i < BLK * DQK; i += 256) {
            int r = i >> 6, d = i & 63;
            kb[r][d] = g_qkvw[(size_t)(n * BLK + r) * OUTD + OK_ + g * DQK + d];
        }
        __syncthreads();
        for (int i = tid; i < HG * BLK; i += 256) {
            int hh = i >> 5, r = i & 31;
            int pos = n * BLK + r;
            float s = NEGI;
            if (pos <= t) {
                float acc = 0.f;
                for (int d = 0; d < DQK; d++) acc += qs[hh][d] * kb[r][d];
                s = acc * SCALE;
            }
            p[hh][c * BLK + r] = s;
        }
        __syncthreads();
    }

    if (tid < HG) {
        float m = NEGI;
        for (int i = 0; i < NSEL * BLK; i++) m = fmaxf(m, p[tid][i]);
        float s = 0.f;
        for (int i = 0; i < NSEL * BLK; i++) { float e = expf(p[tid][i] - m); p[tid][i] = e; s += e; }
        float inv = 1.f / s;
        for (int i = 0; i < NSEL * BLK; i++) p[tid][i] *= inv;
    }
    __syncthreads();

    int hh = tid >> 4, d0 = (tid & 15) << 2;
    float acc[4] = {0.f, 0.f, 0.f, 0.f};
    for (int c = 0; c < NSEL; c++) {
        int n = sidx[c];
        for (int i = tid; i < BLK * DV; i += 256) {
            int r = i >> 6, d = i & 63;
            kb[r][d] = g_qkvw[(size_t)(n * BLK + r) * OUTD + OV + g * DV + d];
        }
        __syncthreads();
        for (int r = 0; r < BLK; r++) {
            float w = p[hh][c * BLK + r];
            acc[0] += w * kb[r][d0 + 0];
            acc[1] += w * kb[r][d0 + 1];
            acc[2] += w * kb[r][d0 + 2];
            acc[3] += w * kb[r][d0 + 3];
        }
        __syncthreads();
    }
    float* outp = g_osel + ((size_t)t * H_ + g * HG + hh) * DV + d0;
    outp[0] = acc[0]; outp[1] = acc[1]; outp[2] = acc[2]; outp[3] = acc[3];
}

// ---------------- sliding-window branch ----------------
// grid (T, G), 256 threads
__global__ void win_kernel() {
    int t = blockIdx.x, g = blockIdx.y;
    __shared__ float qs[HG][DQK];
    __shared__ float kb[BLK][DQK];
    __shared__ float p[HG][WINSZ];
    const int tid = threadIdx.x;

    for (int i = tid; i < HG * DQK; i += 256) {
        int hh = i >> 6, d = i & 63;
        qs[hh][d] = g_qkvw[(size_t)t * OUTD + OQ + (g * HG + hh) * DQK + d];
    }
    __syncthreads();

    const int w0 = t - (WINSZ - 1);
    for (int c = 0; c < WINSZ / BLK; c++) {
        for (int i = tid; i < BLK * DQK; i += 256) {
            int r = i >> 6, d = i & 63;
            int pos = w0 + c * BLK + r;
            int rr = pos < 0 ? 0 : pos;
            kb[r][d] = g_qkvw[(size_t)rr * OUTD + OK_ + g * DQK + d];
        }
        __syncthreads();
        for (int i = tid; i < HG * BLK; i += 256) {
            int hh = i >> 5, r = i & 31;
            int pos = w0 + c * BLK + r;
            float s = NEGI;
            if (pos >= 0) {
                float acc = 0.f;
                for (int d = 0; d < DQK; d++) acc += qs[hh][d] * kb[r][d];
                s = acc * SCALE;
            }
            p[hh][c * BLK + r] = s;
        }
        __syncthreads();
    }

    if (tid < HG) {
        float m = NEGI;
        for (int i = 0; i < WINSZ; i++) m = fmaxf(m, p[tid][i]);
        float s = 0.f;
        for (int i = 0; i < WINSZ; i++) { float e = expf(p[tid][i] - m); p[tid][i] = e; s += e; }
        float inv = 1.f / s;
        for (int i = 0; i < WINSZ; i++) p[tid][i] *= inv;
    }
    __syncthreads();

    int hh = tid >> 4, d0 = (tid & 15) << 2;
    float acc[4] = {0.f, 0.f, 0.f, 0.f};
    for (int c = 0; c < WINSZ / BLK; c++) {
        for (int i = tid; i < BLK * DV; i += 256) {
            int r = i >> 6, d = i & 63;
            int pos = w0 + c * BLK + r;
            int rr = pos < 0 ? 0 : pos;
            kb[r][d] = g_qkvw[(size_t)rr * OUTD + OV + g * DV + d];
        }
        __syncthreads();
        for (int r = 0; r < BLK; r++) {
            float w = p[hh][c * BLK + r];     // exactly 0 for masked positions
            acc[0] += w * kb[r][d0 + 0];
            acc[1] += w * kb[r][d0 + 1];
            acc[2] += w * kb[r][d0 + 2];
            acc[3] += w * kb[r][d0 + 3];
        }
        __syncthreads();
    }
    float* outp = g_owin + ((size_t)t * H_ + g * HG + hh) * DV + d0;
    outp[0] = acc[0]; outp[1] = acc[1]; outp[2] = acc[2]; outp[3] = acc[3];
}

// ---------------- sigmoid-gated combine ----------------
__global__ void combine_kernel() {
    int idx = blockIdx.x * blockDim.x + threadIdx.x;
    if (idx >= T_ * H_ * DV) return;
    int h = (idx >> 6) & 31;
    int t = idx >> 11;
    const float* wrow = g_qkvw + (size_t)t * OUTD + OW + h * 3;
    float g0 = 1.f / (1.f + expf(-wrow[0]));
    float g1 = 1.f / (1.f + expf(-wrow[1]));
    float g2 = 1.f / (1.f + expf(-wrow[2]));
    g_ocomb[idx] = g0 * g_ocmp[idx] + g1 * g_osel[idx] + g2 * g_owin[idx];
}

// ---------------- launch ----------------
extern "C" void kernel_launch(void* const* d_in, const int* in_sizes, int n_in,
                              void* d_out, int out_size) {
    const float* x    = (const float*)d_in[0];   // hidden_states [T,1,HID]
    const float* cosp = (const float*)d_in[1];   // [T,DQK]
    const float* sinp = (const float*)d_in[2];   // [T,DQK]
    const float* wqkv = (const float*)d_in[3];   // [HID,OUTD]
    const float* ow   = (const float*)d_in[4];   // [H*DV,HID]
    // d_in[5] = cu_seqlens (single sequence; unused)
    float* out = (float*)d_out;                  // [T,1,HID] fp32

    float *qkvw_p, *ocomb_p;
    cudaGetSymbolAddress((void**)&qkvw_p, g_qkvw);
    cudaGetSymbolAddress((void**)&ocomb_p, g_ocomb);

    dim3 g1((OUTD + 127) / 128, T_ / 128);
    sgemm_kernel<<<g1, 256>>>(x, wqkv, qkvw_p, T_, OUTD, HID);

    rope_kernel<<<T_, 256>>>(cosp, sinp);
    pool_kernel<<<(NB * G_ * DQK + 255) / 256, 256>>>();

    dim3 gt(T_, G_);
    cmp_kernel<<<gt, 128>>>();
    sel_kernel<<<gt, 256>>>();
    win_kernel<<<gt, 256>>>();

    combine_kernel<<<(T_ * H_ * DV + 255) / 256, 256>>>();

    dim3 g2(HID / 128, T_ / 128);
    sgemm_kernel<<<g2, 256>>>(ocomb_p, ow, out, T_, HID, HID);
}

// round 2
// speedup vs baseline: 1.3698x; 1.3698x over previous
#include <cuda_runtime.h>
#include <math.h>

// ---------------- problem constants ----------------
namespace {
constexpr int T_    = 2048;
constexpr int HID   = 2048;
constexpr int H_    = 32;
constexpr int HKV   = 2;
constexpr int DQK   = 64;
constexpr int DV    = 64;
constexpr int G_    = 2;
constexpr int HG    = 16;
constexpr int BLK   = 32;
constexpr int NSEL  = 8;
constexpr int WINSZ = 256;
constexpr int NB    = 64;
constexpr int OUTD  = 2400;
constexpr int OQ = 0;
constexpr int OK_ = 2048;
constexpr int OV  = 2176;
constexpr int OW  = 2304;
constexpr float SCALE = 0.125f;
constexpr float NEGI  = -1e30f;
constexpr int TT = 8;   // cmp: query timesteps per block
}

// ---------------- scratch ----------------
__device__ float g_qkvw[(size_t)T_ * OUTD];
__device__ float g_kcmp[NB * G_ * DQK];
__device__ float g_vcmp[NB * G_ * DV];
__device__ float g_ocmp[(size_t)T_ * H_ * DV];
__device__ float g_osel[(size_t)T_ * H_ * DV];
__device__ float g_owin[(size_t)T_ * H_ * DV];
__device__ float g_ocomb[(size_t)T_ * H_ * DV];
__device__ int   g_selidx[T_ * G_ * NSEL];

// ---------------- SGEMM: 128x128 tile, BK=16, double-buffered ----------------
__global__ void sgemm16(const float* __restrict__ A, const float* __restrict__ B,
                        float* __restrict__ C, int M, int N, int K) {
    __shared__ float As[2][16][128];
    __shared__ float Bs[2][16][128];
    const int tid = threadIdx.x;               // 256
    const int bx = blockIdx.x, by = blockIdx.y;
    const int tx = tid & 15, ty = tid >> 4;
    const int aRow = tid >> 2;                 // 0..63 (and +64)
    const int aCol = (tid & 3) << 2;           // 0,4,8,12
    const int bRow = tid >> 5;                 // 0..7 (and +8)
    const int bCol = (tid & 31) << 2;
    const int cColBase = bx * 128;
    const float* Aptr = A + (size_t)(by * 128) * K;

    float acc[8][8];
#pragma unroll
    for (int i = 0; i < 8; i++)
#pragma unroll
        for (int j = 0; j < 8; j++) acc[i][j] = 0.f;

    auto loadA = [&](int k0, float4& a0, float4& a1) {
        a0 = *reinterpret_cast<const float4*>(Aptr + (size_t)aRow * K + k0 + aCol);
        a1 = *reinterpret_cast<const float4*>(Aptr + (size_t)(aRow + 64) * K + k0 + aCol);
    };
    auto loadB = [&](int k0, float4& b0, float4& b1) {
        int gc = cColBase + bCol;
        b0 = make_float4(0.f, 0.f, 0.f, 0.f); b1 = b0;
        if (gc < N) {
            b0 = *reinterpret_cast<const float4*>(B + (size_t)(k0 + bRow) * N + gc);
            b1 = *reinterpret_cast<const float4*>(B + (size_t)(k0 + bRow + 8) * N + gc);
        }
    };
    auto storeA = [&](int buf, float4 a0, float4 a1) {
        As[buf][aCol + 0][aRow] = a0.x; As[buf][aCol + 1][aRow] = a0.y;
        As[buf][aCol + 2][aRow] = a0.z; As[buf][aCol + 3][aRow] = a0.w;
        As[buf][aCol + 0][aRow + 64] = a1.x; As[buf][aCol + 1][aRow + 64] = a1.y;
        As[buf][aCol + 2][aRow + 64] = a1.z; As[buf][aCol + 3][aRow + 64] = a1.w;
    };
    auto storeB = [&](int buf, float4 b0, float4 b1) {
        *reinterpret_cast<float4*>(&Bs[buf][bRow][bCol]) = b0;
        *reinterpret_cast<float4*>(&Bs[buf][bRow + 8][bCol]) = b1;
    };

    float4 a0, a1, b0, b1;
    loadA(0, a0, a1); loadB(0, b0, b1);
    storeA(0, a0, a1); storeB(0, b0, b1);
    __syncthreads();
    int cur = 0;
    for (int k0 = 0; k0 < K; k0 += 16) {
        const bool has_next = (k0 + 16) < K;
        float4 na0, na1, nb0, nb1;
        if (has_next) { loadA(k0 + 16, na0, na1); loadB(k0 + 16, nb0, nb1); }
        float ar[8], br[8];
#pragma unroll
        for (int kk = 0; kk < 16; kk++) {
#pragma unroll
            for (int i = 0; i < 8; i++) ar[i] = As[cur][kk][ty * 8 + i];
#pragma unroll
            for (int j = 0; j < 8; j++) br[j] = Bs[cur][kk][tx * 8 + j];
#pragma unroll
            for (int i = 0; i < 8; i++)
#pragma unroll
                for (int j = 0; j < 8; j++) acc[i][j] += ar[i] * br[j];
        }
        if (has_next) {
            storeA(cur ^ 1, na0, na1); storeB(cur ^ 1, nb0, nb1);
            __syncthreads();
            cur ^= 1;
        }
    }
#pragma unroll
    for (int i = 0; i < 8; i++) {
        int row = by * 128 + ty * 8 + i;
#pragma unroll
        for (int j = 0; j < 8; j += 4) {
            int col = cColBase + tx * 8 + j;
            if (col < N) {
                *reinterpret_cast<float4*>(C + (size_t)row * N + col) =
                    make_float4(acc[i][j], acc[i][j + 1], acc[i][j + 2], acc[i][j + 3]);
            }
        }
    }
}

// ---------------- RoPE ----------------
__global__ void rope_kernel(const float* __restrict__ cosp, const float* __restrict__ sinp) {
    int t = blockIdx.x;
    float* row = g_qkvw + (size_t)t * OUTD;
    for (int i = threadIdx.x; i < (H_ + HKV) * 32; i += blockDim.x) {
        int head = i >> 5, dp = i & 31;
        float* base = (head < H_) ? (row + OQ + head * DQK)
                                  : (row + OK_ + (head - H_) * DQK);
        float x1 = base[dp], x2 = base[dp + 32];
        float c1 = cosp[t * DQK + dp],      s1 = sinp[t * DQK + dp];
        float c2 = cosp[t * DQK + dp + 32], s2 = sinp[t * DQK + dp + 32];
        base[dp]      = x1 * c1 - x2 * s1;
        base[dp + 32] = x2 * c2 + x1 * s2;
    }
}

// ---------------- mean pool ----------------
__global__ void pool_kernel() {
    int idx = blockIdx.x * blockDim.x + threadIdx.x;
    if (idx >= NB * G_ * DQK) return;
    int nb = idx / (G_ * DQK);
    int g  = (idx / DQK) % G_;
    int d  = idx % DQK;
    float sk = 0.f, sv = 0.f;
    for (int i = 0; i < BLK; i++) {
        const float* r = g_qkvw + (size_t)(nb * BLK + i) * OUTD;
        sk += r[OK_ + g * DQK + d];
        sv += r[OV  + g * DV  + d];
    }
    g_kcmp[idx] = sk * (1.f / BLK);
    g_vcmp[idx] = sv * (1.f / BLK);
}

// ---------------- compressed branch + top-k, tiled over TT timesteps ----------------
// grid (T/TT, G), 256 threads, dynamic smem
__global__ void cmp_kernel2() {
    extern __shared__ float sm[];
    float* kbuf = sm;                 // 64*64 (K then V)
    float* p    = sm + 4096;          // TT*16*64
    float* imp  = p + TT * 16 * 64;   // TT*64
    const int t0 = blockIdx.x * TT;
    const int g  = blockIdx.y;
    const int tid = threadIdx.x;

    // load k_cmp for group g (float4)
    for (int i = tid; i < NB * DQK / 4; i += 256) {
        int n = i >> 4, d4 = (i & 15) << 2;
        *reinterpret_cast<float4*>(&kbuf[n * 64 + d4]) =
            *reinterpret_cast<const float4*>(&g_kcmp[(n * G_ + g) * DQK + d4]);
    }
    __syncthreads();

    // scores: row = (tt,hh), 2 threads per row (n halves), q in registers
    const int row = tid >> 1;
    const int tt = row >> 4, hh = row & 15;
    const int t = t0 + tt;
    const int half = tid & 1;
    {
        float4 q[16];
        const float4* qp = reinterpret_cast<const float4*>(
            g_qkvw + (size_t)t * OUTD + OQ + (g * HG + hh) * DQK);
#pragma unroll
        for (int i = 0; i < 16; i++) q[i] = qp[i];
        const int nvis = (t + 1) >> 5;
        float* prow = p + row * 64;
        for (int n = half * 32; n < half * 32 + 32; n++) {
            float s = NEGI;
            if (n < nvis) {
                float a = 0.f;
#pragma unroll
                for (int i = 0; i < 16; i++) {
                    float4 kv = *reinterpret_cast<float4*>(&kbuf[n * 64 + i * 4]);
                    a += q[i].x * kv.x + q[i].y * kv.y + q[i].z * kv.z + q[i].w * kv.w;
                }
                s = a * SCALE;
            }
            prow[n] = s;
        }
    }
    __syncthreads();

    // overwrite kbuf with v_cmp (completes by next barrier); softmax in parallel
    for (int i = tid; i < NB * DV / 4; i += 256) {
        int n = i >> 4, d4 = (i & 15) << 2;
        *reinterpret_cast<float4*>(&kbuf[n * 64 + d4]) =
            *reinterpret_cast<const float4*>(&g_vcmp[(n * G_ + g) * DV + d4]);
    }
    if (tid < 128) {
        float* pr = p + tid * 64;
        int tloc = t0 + (tid >> 4);
        int nv = (tloc + 1) >> 5;
        if (nv == 0) {
            for (int n = 0; n < 64; n++) pr[n] = 0.f;
        } else {
            float m = NEGI;
            for (int n = 0; n < 64; n++) m = fmaxf(m, pr[n]);
            float s = 0.f;
            for (int n = 0; n < 64; n++) { float e = __expf(pr[n] - m); pr[n] = e; s += e; }
            float inv = 1.f / s;
            for (int n = 0; n < 64; n++) pr[n] *= inv;
        }
    }
    __syncthreads();

    // importance (head-summed) + forces + causal mask
    for (int i = tid; i < TT * NB; i += 256) {
        int tti = i >> 6, n = i & 63;
        int tloc = t0 + tti, cur = tloc >> 5;
        float v;
        if (n > cur) v = NEGI;
        else {
            v = 0.f;
            for (int h2 = 0; h2 < 16; h2++) v += p[(tti * 16 + h2) * 64 + n];
            if (n == 0)   v += 1e4f;
            if (n == cur) v += 1e4f;
        }
        imp[i] = v;
    }
    __syncthreads();

    // top-8 per timestep: one warp per tt, shuffle reduce, lowest-index tie break
    {
        int wid = tid >> 5, lane = tid & 31;
        if (wid < TT) {
            float v0 = imp[wid * 64 + lane];
            float v1 = imp[wid * 64 + 32 + lane];
            int* outp = g_selidx + ((t0 + wid) * G_ + g) * NSEL;
            for (int j = 0; j < NSEL; j++) {
                float bv = v0; int bi = lane;
                if (v1 > bv) { bv = v1; bi = lane + 32; }
#pragma unroll
                for (int off = 16; off; off >>= 1) {
                    float ov = __shfl_xor_sync(0xffffffffu, bv, off);
                    int   oi = __shfl_xor_sync(0xffffffffu, bi, off);
                    if (ov > bv || (ov == bv && oi < bi)) { bv = ov; bi = oi; }
                }
                if (lane == 0) outp[j] = bi;
                if (bi == lane)      v0 = -2e30f;
                if (bi == lane + 32) v1 = -2e30f;
            }
        }
    }

    // o_cmp = p @ v_cmp : thread = (tt,hh) row, half of d
    {
        const int nv = (t + 1) >> 5;
        float acc[32];
#pragma unroll
        for (int i = 0; i < 32; i++) acc[i] = 0.f;
        const float* pr = p + row * 64;
        for (int n = 0; n < nv; n++) {
            float w = pr[n];
            const float* vr = kbuf + n * 64 + half * 32;
#pragma unroll
            for (int i = 0; i < 8; i++) {
                float4 v4 = *reinterpret_cast<const float4*>(&vr[i * 4]);
                acc[i * 4 + 0] += w * v4.x; acc[i * 4 + 1] += w * v4.y;
                acc[i * 4 + 2] += w * v4.z; acc[i * 4 + 3] += w * v4.w;
            }
        }
        float* op = g_ocmp + ((size_t)t * H_ + g * HG + hh) * DV + half * 32;
#pragma unroll
        for (int i = 0; i < 8; i++)
            *reinterpret_cast<float4*>(&op[i * 4]) =
                make_float4(acc[i * 4], acc[i * 4 + 1], acc[i * 4 + 2], acc[i * 4 + 3]);
    }
}

// ---------------- selection branch ----------------
// grid (T, G), 256 threads, dynamic smem
__global__ void sel_kernel2() {
    extern __shared__ float sm[];
    float* kbuf = sm;                 // 256*64 (K then V)
    float* p    = sm + 256 * 64;      // 16*256
    float* qs   = p + 16 * 256;       // 16*64
    __shared__ int sidx[NSEL];
    const int t = blockIdx.x, g = blockIdx.y, tid = threadIdx.x;

    if (tid < NSEL) sidx[tid] = g_selidx[(t * G_ + g) * NSEL + tid];
    for (int i = tid; i < HG * DQK / 4; i += 256) {
        int hh = i >> 4, d4 = (i & 15) << 2;
        *reinterpret_cast<float4*>(&qs[hh * 64 + d4]) =
            *reinterpret_cast<const float4*>(g_qkvw + (size_t)t * OUTD + OQ + (g * HG + hh) * DQK + d4);
    }
    __syncthreads();

    // bulk K load: 4096 float4, 16 per thread, no intermediate syncs
    for (int i = tid; i < NSEL * BLK * DQK / 4; i += 256) {
        int c = i >> 9, r = (i >> 4) & 31, d4 = (i & 15) << 2;
        int rowg = sidx[c] * BLK + r;
        *reinterpret_cast<float4*>(&kbuf[(c * 32 + r) * 64 + d4]) =
            *reinterpret_cast<const float4*>(g_qkvw + (size_t)rowg * OUTD + OK_ + g * DQK + d4);
    }
    __syncthreads();

    // scores: thread = (hh, r mod 16), q cached in registers
    const int hh = tid >> 4, rb = tid & 15;
    {
        float4 q[16];
#pragma unroll
        for (int i = 0; i < 16; i++) q[i] = *reinterpret_cast<float4*>(&qs[hh * 64 + i * 4]);
        for (int k = 0; k < 16; k++) {
            int r = rb + k * 16;
            int pos = sidx[r >> 5] * BLK + (r & 31);
            float s = NEGI;
            if (pos <= t) {
                float a = 0.f;
#pragma unroll
                for (int i = 0; i < 16; i++) {
                    float4 kv = *reinterpret_cast<float4*>(&kbuf[r * 64 + i * 4]);
                    a += q[i].x * kv.x + q[i].y * kv.y + q[i].z * kv.z + q[i].w * kv.w;
                }
                s = a * SCALE;
            }
            p[hh * 256 + r] = s;
        }
    }
    __syncthreads();

    // bulk V load (overwrites kbuf), softmax runs while loads are in flight
    for (int i = tid; i < NSEL * BLK * DV / 4; i += 256) {
        int c = i >> 9, r = (i >> 4) & 31, d4 = (i & 15) << 2;
        int rowg = sidx[c] * BLK + r;
        *reinterpret_cast<float4*>(&kbuf[(c * 32 + r) * 64 + d4]) =
            *reinterpret_cast<const float4*>(g_qkvw + (size_t)rowg * OUTD + OV + g * DV + d4);
    }
    {
        int wid = tid >> 5, lane = tid & 31;
#pragma unroll
        for (int rr = 0; rr < 2; rr++) {
            float* pr = p + (wid * 2 + rr) * 256;
            float v[8];
            float m = NEGI;
#pragma unroll
            for (int i = 0; i < 8; i++) { v[i] = pr[i * 32 + lane]; m = fmaxf(m, v[i]); }
#pragma unroll
            for (int off = 16; off; off >>= 1) m = fmaxf(m, __shfl_xor_sync(0xffffffffu, m, off));
            float s = 0.f;
#pragma unroll
            for (int i = 0; i < 8; i++) { v[i] = __expf(v[i] - m); s += v[i]; }
#pragma unroll
            for (int off = 16; off; off >>= 1) s += __shfl_xor_sync(0xffffffffu, s, off);
            float inv = 1.f / s;
#pragma unroll
            for (int i = 0; i < 8; i++) pr[i * 32 + lane] = v[i] * inv;
        }
    }
    __syncthreads();

    // o = p @ V
    {
        const int d0 = (tid & 15) << 2;
        const float* pr = p + hh * 256;
        float4 acc = make_float4(0.f, 0.f, 0.f, 0.f);
        for (int r = 0; r < 256; r++) {
            float w = pr[r];
            float4 v4 = *reinterpret_cast<float4*>(&kbuf[r * 64 + d0]);
            acc.x += w * v4.x; acc.y += w * v4.y; acc.z += w * v4.z; acc.w += w * v4.w;
        }
        *reinterpret_cast<float4*>(g_osel + ((size_t)t * H_ + g * HG + hh) * DV + d0) = acc;
    }
}

// ---------------- sliding-window branch ----------------
// grid (T, G), 256 threads, dynamic smem
__global__ void win_kernel2() {
    extern __shared__ float sm[];
    float* kbuf = sm;
    float* p    = sm + 256 * 64;
    float* qs   = p + 16 * 256;
    const int t = blockIdx.x, g = blockIdx.y, tid = threadIdx.x;
    const int w0 = t - (WINSZ - 1);

    for (int i = tid; i < HG * DQK / 4; i += 256) {
        int hh = i >> 4, d4 = (i & 15) << 2;
        *reinterpret_cast<float4*>(&qs[hh * 64 + d4]) =
            *reinterpret_cast<const float4*>(g_qkvw + (size_t)t * OUTD + OQ + (g * HG + hh) * DQK + d4);
    }
    // bulk K window load
    for (int i = tid; i < WINSZ * DQK / 4; i += 256) {
        int r = i >> 4, d4 = (i & 15) << 2;
        int pos = w0 + r;
        int rc = pos < 0 ? 0 : pos;
        *reinterpret_cast<float4*>(&kbuf[r * 64 + d4]) =
            *reinterpret_cast<const float4*>(g_qkvw + (size_t)rc * OUTD + OK_ + g * DQK + d4);
    }
    __syncthreads();

    const int hh = tid >> 4, rb = tid & 15;
    {
        float4 q[16];
#pragma unroll
        for (int i = 0; i < 16; i++) q[i] = *reinterpret_cast<float4*>(&qs[hh * 64 + i * 4]);
        for (int k = 0; k < 16; k++) {
            int r = rb + k * 16;
            float s = NEGI;
            if (w0 + r >= 0) {
                float a = 0.f;
#pragma unroll
                for (int i = 0; i < 16; i++) {
                    float4 kv = *reinterpret_cast<float4*>(&kbuf[r * 64 + i * 4]);
                    a += q[i].x * kv.x + q[i].y * kv.y + q[i].z * kv.z + q[i].w * kv.w;
                }
                s = a * SCALE;
            }
            p[hh * 256 + r] = s;
        }
    }
    __syncthreads();

    // bulk V window load + softmax
    for (int i = tid; i < WINSZ * DV / 4; i += 256) {
        int r = i >> 4, d4 = (i & 15) << 2;
        int pos = w0 + r;
        int rc = pos < 0 ? 0 : pos;
        *reinterpret_cast<float4*>(&kbuf[r * 64 + d4]) =
            *reinterpret_cast<const float4*>(g_qkvw + (size_t)rc * OUTD + OV + g * DV + d4);
    }
    {
        int wid = tid >> 5, lane = tid & 31;
#pragma unroll
        for (int rr = 0; rr < 2; rr++) {
            float* pr = p + (wid * 2 + rr) * 256;
            float v[8];
            float m = NEGI;
#pragma unroll
            for (int i = 0; i < 8; i++) { v[i] = pr[i * 32 + lane]; m = fmaxf(m, v[i]); }
#pragma unroll
            for (int off = 16; off; off >>= 1) m = fmaxf(m, __shfl_xor_sync(0xffffffffu, m, off));
            float s = 0.f;
#pragma unroll
            for (int i = 0; i < 8; i++) { v[i] = __expf(v[i] - m); s += v[i]; }
#pragma unroll
            for (int off = 16; off; off >>= 1) s += __shfl_xor_sync(0xffffffffu, s, off);
            float inv = 1.f / s;
#pragma unroll
            for (int i = 0; i < 8; i++) pr[i * 32 + lane] = v[i] * inv;
        }
    }
    __syncthreads();

    {
        const int d0 = (tid & 15) << 2;
        const float* pr = p + hh * 256;
        float4 acc = make_float4(0.f, 0.f, 0.f, 0.f);
        for (int r = 0; r < 256; r++) {
            float w = pr[r];   // exactly 0 for masked rows
            float4 v4 = *reinterpret_cast<float4*>(&kbuf[r * 64 + d0]);
            acc.x += w * v4.x; acc.y += w * v4.y; acc.z += w * v4.z; acc.w += w * v4.w;
        }
        *reinterpret_cast<float4*>(g_owin + ((size_t)t * H_ + g * HG + hh) * DV + d0) = acc;
    }
}

// ---------------- gated combine ----------------
__global__ void combine_kernel() {
    int idx = blockIdx.x * blockDim.x + threadIdx.x;
    if (idx >= T_ * H_ * DV) return;
    int h = (idx >> 6) & 31;
    int t = idx >> 11;
    const float* wrow = g_qkvw + (size_t)t * OUTD + OW + h * 3;
    float g0 = 1.f / (1.f + __expf(-wrow[0]));
    float g1 = 1.f / (1.f + __expf(-wrow[1]));
    float g2 = 1.f / (1.f + __expf(-wrow[2]));
    g_ocomb[idx] = g0 * g_ocmp[idx] + g1 * g_osel[idx] + g2 * g_owin[idx];
}

// ---------------- launch ----------------
extern "C" void kernel_launch(void* const* d_in, const int* in_sizes, int n_in,
                              void* d_out, int out_size) {
    const float* x    = (const float*)d_in[0];
    const float* cosp = (const float*)d_in[1];
    const float* sinp = (const float*)d_in[2];
    const float* wqkv = (const float*)d_in[3];
    const float* ow   = (const float*)d_in[4];
    float* out = (float*)d_out;

    float *qkvw_p, *ocomb_p;
    cudaGetSymbolAddress((void**)&qkvw_p, g_qkvw);
    cudaGetSymbolAddress((void**)&ocomb_p, g_ocomb);

    const int CMP_SMEM = (64 * 64 + TT * 16 * 64 + TT * 64) * 4;       // 51200 B
    const int SW_SMEM  = (256 * 64 + 16 * 256 + 16 * 64) * 4;         // 86016 B
    cudaFuncSetAttribute((const void*)cmp_kernel2, cudaFuncAttributeMaxDynamicSharedMemorySize, CMP_SMEM);
    cudaFuncSetAttribute((const void*)sel_kernel2, cudaFuncAttributeMaxDynamicSharedMemorySize, SW_SMEM);
    cudaFuncSetAttribute((const void*)win_kernel2, cudaFuncAttributeMaxDynamicSharedMemorySize, SW_SMEM);

    dim3 g1((OUTD + 127) / 128, T_ / 128);
    sgemm16<<<g1, 256>>>(x, wqkv, qkvw_p, T_, OUTD, HID);

    rope_kernel<<<T_, 256>>>(cosp, sinp);
    pool_kernel<<<(NB * G_ * DQK + 255) / 256, 256>>>();

    dim3 gc(T_ / TT, G_);
    cmp_kernel2<<<gc, 256, CMP_SMEM>>>();

    dim3 gt(T_, G_);
    sel_kernel2<<<gt, 256, SW_SMEM>>>();
    win_kernel2<<<gt, 256, SW_SMEM>>>();

    combine_kernel<<<(T_ * H_ * DV + 255) / 256, 256>>>();

    dim3 g2(HID / 128, T_ / 128);
    sgemm16<<<g2, 256>>>(ocomb_p, ow, out, T_, HID, HID);
}

// round 3
// speedup vs baseline: 1.6308x; 1.1906x over previous
#include <cuda_runtime.h>
#include <cuda_bf16.h>
#include <math.h>
#include <stdint.h>

// ---------------- problem constants ----------------
namespace {
constexpr int T_    = 2048;
constexpr int HID   = 2048;
constexpr int H_    = 32;
constexpr int HKV   = 2;
constexpr int DQK   = 64;
constexpr int DV    = 64;
constexpr int G_    = 2;
constexpr int HG    = 16;
constexpr int BLK   = 32;
constexpr int NSEL  = 8;
constexpr int WINSZ = 256;
constexpr int NB    = 64;
constexpr int OUTD  = 2400;
constexpr int OQ = 0;
constexpr int OK_ = 2048;
constexpr int OV  = 2176;
constexpr int OW  = 2304;
constexpr float SCALE = 0.125f;
constexpr float NEGI  = -1e30f;
constexpr int TT = 8;

// bf16x3 GEMM tiles
constexpr int ASTR = 40;    // 32 + 8 pad (bf16 elems)
constexpr int BSTR = 136;   // 128 + 8 pad
constexpr int ASZB = 128 * ASTR * 2;   // bytes per A buffer = 10240
constexpr int BSZB = 32 * BSTR * 2;    // bytes per B buffer = 8704
constexpr int GEMM_SMEM = 4 * ASZB + 4 * BSZB;  // 75776 B
}

// ---------------- scratch ----------------
__device__ float g_qkvw[(size_t)T_ * OUTD];
__device__ float g_kcmp[NB * G_ * DQK];
__device__ float g_vcmp[NB * G_ * DV];
__device__ float g_ocmp[(size_t)T_ * H_ * DV];
__device__ float g_osel[(size_t)T_ * H_ * DV];
__device__ float g_owin[(size_t)T_ * H_ * DV];
__device__ float g_ocomb[(size_t)T_ * H_ * DV];
__device__ int   g_selidx[T_ * G_ * NSEL];

// ---------------- mma / ldmatrix helpers ----------------
__device__ __forceinline__ uint32_t smem_u32(const void* p) {
    return (uint32_t)__cvta_generic_to_shared(p);
}
__device__ __forceinline__ void ldsm_x4(uint32_t addr, uint32_t& r0, uint32_t& r1,
                                        uint32_t& r2, uint32_t& r3) {
    asm volatile("ldmatrix.sync.aligned.m8n8.x4.shared.b16 {%0,%1,%2,%3}, [%4];"
                 : "=r"(r0), "=r"(r1), "=r"(r2), "=r"(r3) : "r"(addr));
}
__device__ __forceinline__ void ldsm_x2t(uint32_t addr, uint32_t& r0, uint32_t& r1) {
    asm volatile("ldmatrix.sync.aligned.m8n8.x2.trans.shared.b16 {%0,%1}, [%2];"
                 : "=r"(r0), "=r"(r1) : "r"(addr));
}
__device__ __forceinline__ void mma_bf16(float* c, const uint32_t* a, const uint32_t* b) {
    asm volatile(
        "mma.sync.aligned.m16n8k16.row.col.f32.bf16.bf16.f32 "
        "{%0,%1,%2,%3}, {%4,%5,%6,%7}, {%8,%9}, {%0,%1,%2,%3};"
        : "+f"(c[0]), "+f"(c[1]), "+f"(c[2]), "+f"(c[3])
        : "r"(a[0]), "r"(a[1]), "r"(a[2]), "r"(a[3]), "r"(b[0]), "r"(b[1]));
}
// split one float into bf16 hi + bf16 lo
__device__ __forceinline__ void split2(float x, float y, uint32_t& hi, uint32_t& lo) {
    __nv_bfloat16 xh = __float2bfloat16(x);
    __nv_bfloat16 yh = __float2bfloat16(y);
    __nv_bfloat16 xl = __float2bfloat16(x - __bfloat162float(xh));
    __nv_bfloat16 yl = __float2bfloat16(y - __bfloat162float(yh));
    __nv_bfloat162 h2 = __nv_bfloat162(xh, yh);
    __nv_bfloat162 l2 = __nv_bfloat162(xl, yl);
    hi = *reinterpret_cast<uint32_t*>(&h2);
    lo = *reinterpret_cast<uint32_t*>(&l2);
}

// ---------------- bf16x3 tensor-core GEMM ----------------
// C[M,N] = A[M,K] @ B[K,N], fp32 in/out, ~1e-5 relative accuracy.
// block 128x128, BK=32, 256 threads (8 warps, 2(M) x 4(N)), warp tile 64x32.
__global__ void __launch_bounds__(256, 1)
gemm_bf16x3(const float* __restrict__ A, const float* __restrict__ B,
            float* __restrict__ C, int M, int N, int K) {
    extern __shared__ char smraw[];
    char* sAh = smraw;                       // [2][128*ASTR] bf16
    char* sAl = smraw + 2 * ASZB;
    char* sBh = smraw + 4 * ASZB;            // [2][32*BSTR] bf16
    char* sBl = smraw + 4 * ASZB + 2 * BSZB;

    const int tid  = threadIdx.x;
    const int lane = tid & 31;
    const int wid  = tid >> 5;
    const int wm   = wid & 1;                // 0..1  (64 rows each)
    const int wn   = wid >> 1;               // 0..3  (32 cols each)
    const int bx = blockIdx.x, by = blockIdx.y;
    const int cColBase = bx * 128;

    // global load coords
    const int aRow = tid >> 1;               // 0..127
    const int aCol = (tid & 1) << 4;         // 0 / 16  (+0,4,8,12)
    const int bRow = tid >> 3;               // 0..31
    const int bCol = (tid & 7) << 4;         // 0..112  (+0,4,8,12)
    const float* Aptr = A + (size_t)(by * 128 + aRow) * K + aCol;

    float4 af[4], bf[4];
    auto gload = [&](int k0) {
#pragma unroll
        for (int j = 0; j < 4; j++)
            af[j] = *reinterpret_cast<const float4*>(Aptr + k0 + j * 4);
#pragma unroll
        for (int j = 0; j < 4; j++) {
            int gc = cColBase + bCol + j * 4;
            bf[j] = make_float4(0.f, 0.f, 0.f, 0.f);
            if (gc < N)
                bf[j] = *reinterpret_cast<const float4*>(B + (size_t)(k0 + bRow) * N + gc);
        }
    };
    auto sstore = [&](int buf) {
        char* ah = sAh + buf * ASZB; char* al = sAl + buf * ASZB;
        char* bh = sBh + buf * BSZB; char* bl = sBl + buf * BSZB;
#pragma unroll
        for (int j = 0; j < 4; j++) {
            uint32_t h0, l0, h1, l1;
            split2(af[j].x, af[j].y, h0, l0);
            split2(af[j].z, af[j].w, h1, l1);
            int off = (aRow * ASTR + aCol + j * 4) * 2;
            *reinterpret_cast<uint32_t*>(ah + off)     = h0;
            *reinterpret_cast<uint32_t*>(ah + off + 4) = h1;
            *reinterpret_cast<uint32_t*>(al + off)     = l0;
            *reinterpret_cast<uint32_t*>(al + off + 4) = l1;
        }
#pragma unroll
        for (int j = 0; j < 4; j++) {
            uint32_t h0, l0, h1, l1;
            split2(bf[j].x, bf[j].y, h0, l0);
            split2(bf[j].z, bf[j].w, h1, l1);
            int off = (bRow * BSTR + bCol + j * 4) * 2;
            *reinterpret_cast<uint32_t*>(bh + off)     = h0;
            *reinterpret_cast<uint32_t*>(bh + off + 4) = h1;
            *reinterpret_cast<uint32_t*>(bl + off)     = l0;
            *reinterpret_cast<uint32_t*>(bl + off + 4) = l1;
        }
    };

    float acc[4][4][4];
#pragma unroll
    for (int i = 0; i < 4; i++)
#pragma unroll
        for (int j = 0; j < 4; j++)
#pragma unroll
            for (int r = 0; r < 4; r++) acc[i][j][r] = 0.f;

    // lane-invariant parts of ldmatrix addresses
    const int aLaneRow = wm * 64 + (lane & 15);     // + mt*16
    const int aLaneK   = (lane >> 4) << 3;          // + kk
    const int bLaneK   = lane & 15;                 // + kk
    const int bLaneCol = wn * 32;                   // + nt*8
    const uint32_t sAh0 = smem_u32(sAh), sAl0 = smem_u32(sAl);
    const uint32_t sBh0 = smem_u32(sBh), sBl0 = smem_u32(sBl);

    gload(0);
    sstore(0);
    __syncthreads();
    int cur = 0;
    for (int k0 = 0; k0 < K; k0 += 32) {
        const bool has_next = (k0 + 32) < K;
        if (has_next) gload(k0 + 32);

        const uint32_t aHiB = sAh0 + cur * ASZB, aLoB = sAl0 + cur * ASZB;
        const uint32_t bHiB = sBh0 + cur * BSZB, bLoB = sBl0 + cur * BSZB;
#pragma unroll
        for (int kk = 0; kk < 32; kk += 16) {
            uint32_t ah[4][4], al[4][4], bh[4][2], bl[4][2];
#pragma unroll
            for (int mt = 0; mt < 4; mt++) {
                uint32_t off = ((aLaneRow + mt * 16) * ASTR + kk + aLaneK) * 2;
                ldsm_x4(aHiB + off, ah[mt][0], ah[mt][1], ah[mt][2], ah[mt][3]);
                ldsm_x4(aLoB + off, al[mt][0], al[mt][1], al[mt][2], al[mt][3]);
            }
#pragma unroll
            for (int nt = 0; nt < 4; nt++) {
                uint32_t off = ((kk + bLaneK) * BSTR + bLaneCol + nt * 8) * 2;
                ldsm_x2t(bHiB + off, bh[nt][0], bh[nt][1]);
                ldsm_x2t(bLoB + off, bl[nt][0], bl[nt][1]);
            }
#pragma unroll
            for (int mt = 0; mt < 4; mt++)
#pragma unroll
                for (int nt = 0; nt < 4; nt++) {
                    mma_bf16(acc[mt][nt], ah[mt], bh[nt]);
                    mma_bf16(acc[mt][nt], ah[mt], bl[nt]);
                    mma_bf16(acc[mt][nt], al[mt], bh[nt]);
                }
        }
        if (has_next) {
            sstore(cur ^ 1);
            __syncthreads();
            cur ^= 1;
        }
    }

    // epilogue
    const int rBase = by * 128 + wm * 64 + (lane >> 2);
    const int cBase = cColBase + wn * 32 + (lane & 3) * 2;
#pragma unroll
    for (int mt = 0; mt < 4; mt++)
#pragma unroll
        for (int nt = 0; nt < 4; nt++) {
            int r0 = rBase + mt * 16;
            int c0 = cBase + nt * 8;
            if (c0 + 1 < N) {
                C[(size_t)r0 * N + c0]           = acc[mt][nt][0];
                C[(size_t)r0 * N + c0 + 1]       = acc[mt][nt][1];
                C[(size_t)(r0 + 8) * N + c0]     = acc[mt][nt][2];
                C[(size_t)(r0 + 8) * N + c0 + 1] = acc[mt][nt][3];
            }
        }
}

// ---------------- RoPE ----------------
__global__ void rope_kernel(const float* __restrict__ cosp, const float* __restrict__ sinp) {
    int t = blockIdx.x;
    float* row = g_qkvw + (size_t)t * OUTD;
    for (int i = threadIdx.x; i < (H_ + HKV) * 32; i += blockDim.x) {
        int head = i >> 5, dp = i & 31;
        float* base = (head < H_) ? (row + OQ + head * DQK)
                                  : (row + OK_ + (head - H_) * DQK);
        float x1 = base[dp], x2 = base[dp + 32];
        float c1 = cosp[t * DQK + dp],      s1 = sinp[t * DQK + dp];
        float c2 = cosp[t * DQK + dp + 32], s2 = sinp[t * DQK + dp + 32];
        base[dp]      = x1 * c1 - x2 * s1;
        base[dp + 32] = x2 * c2 + x1 * s2;
    }
}

// ---------------- mean pool ----------------
__global__ void pool_kernel() {
    int idx = blockIdx.x * blockDim.x + threadIdx.x;
    if (idx >= NB * G_ * DQK) return;
    int nb = idx / (G_ * DQK);
    int g  = (idx / DQK) % G_;
    int d  = idx % DQK;
    float sk = 0.f, sv = 0.f;
    for (int i = 0; i < BLK; i++) {
        const float* r = g_qkvw + (size_t)(nb * BLK + i) * OUTD;
        sk += r[OK_ + g * DQK + d];
        sv += r[OV  + g * DV  + d];
    }
    g_kcmp[idx] = sk * (1.f / BLK);
    g_vcmp[idx] = sv * (1.f / BLK);
}

// ---------------- compressed branch + top-k ----------------
__global__ void cmp_kernel2() {
    extern __shared__ float sm[];
    float* kbuf = sm;
    float* p    = sm + 4096;
    float* imp  = p + TT * 16 * 64;
    const int t0 = blockIdx.x * TT;
    const int g  = blockIdx.y;
    const int tid = threadIdx.x;

    for (int i = tid; i < NB * DQK / 4; i += 256) {
        int n = i >> 4, d4 = (i & 15) << 2;
        *reinterpret_cast<float4*>(&kbuf[n * 64 + d4]) =
            *reinterpret_cast<const float4*>(&g_kcmp[(n * G_ + g) * DQK + d4]);
    }
    __syncthreads();

    const int row = tid >> 1;
    const int tt = row >> 4, hh = row & 15;
    const int t = t0 + tt;
    const int half = tid & 1;
    {
        float4 q[16];
        const float4* qp = reinterpret_cast<const float4*>(
            g_qkvw + (size_t)t * OUTD + OQ + (g * HG + hh) * DQK);
#pragma unroll
        for (int i = 0; i < 16; i++) q[i] = qp[i];
        const int nvis = (t + 1) >> 5;
        float* prow = p + row * 64;
        for (int n = half * 32; n < half * 32 + 32; n++) {
            float s = NEGI;
            if (n < nvis) {
                float a = 0.f;
#pragma unroll
                for (int i = 0; i < 16; i++) {
                    float4 kv = *reinterpret_cast<float4*>(&kbuf[n * 64 + i * 4]);
                    a += q[i].x * kv.x + q[i].y * kv.y + q[i].z * kv.z + q[i].w * kv.w;
                }
                s = a * SCALE;
            }
            prow[n] = s;
        }
    }
    __syncthreads();

    for (int i = tid; i < NB * DV / 4; i += 256) {
        int n = i >> 4, d4 = (i & 15) << 2;
        *reinterpret_cast<float4*>(&kbuf[n * 64 + d4]) =
            *reinterpret_cast<const float4*>(&g_vcmp[(n * G_ + g) * DV + d4]);
    }
    if (tid < 128) {
        float* pr = p + tid * 64;
        int tloc = t0 + (tid >> 4);
        int nv = (tloc + 1) >> 5;
        if (nv == 0) {
            for (int n = 0; n < 64; n++) pr[n] = 0.f;
        } else {
            float m = NEGI;
            for (int n = 0; n < 64; n++) m = fmaxf(m, pr[n]);
            float s = 0.f;
            for (int n = 0; n < 64; n++) { float e = __expf(pr[n] - m); pr[n] = e; s += e; }
            float inv = 1.f / s;
            for (int n = 0; n < 64; n++) pr[n] *= inv;
        }
    }
    __syncthreads();

    for (int i = tid; i < TT * NB; i += 256) {
        int tti = i >> 6, n = i & 63;
        int tloc = t0 + tti, cur = tloc >> 5;
        float v;
        if (n > cur) v = NEGI;
        else {
            v = 0.f;
            for (int h2 = 0; h2 < 16; h2++) v += p[(tti * 16 + h2) * 64 + n];
            if (n == 0)   v += 1e4f;
            if (n == cur) v += 1e4f;
        }
        imp[i] = v;
    }
    __syncthreads();

    {
        int wid = tid >> 5, lane = tid & 31;
        if (wid < TT) {
            float v0 = imp[wid * 64 + lane];
            float v1 = imp[wid * 64 + 32 + lane];
            int* outp = g_selidx + ((t0 + wid) * G_ + g) * NSEL;
            for (int j = 0; j < NSEL; j++) {
                float bv = v0; int bi = lane;
                if (v1 > bv) { bv = v1; bi = lane + 32; }
#pragma unroll
                for (int off = 16; off; off >>= 1) {
                    float ov = __shfl_xor_sync(0xffffffffu, bv, off);
                    int   oi = __shfl_xor_sync(0xffffffffu, bi, off);
                    if (ov > bv || (ov == bv && oi < bi)) { bv = ov; bi = oi; }
                }
                if (lane == 0) outp[j] = bi;
                if (bi == lane)      v0 = -2e30f;
                if (bi == lane + 32) v1 = -2e30f;
            }
        }
    }

    {
        const int nv = (t + 1) >> 5;
        float acc[32];
#pragma unroll
        for (int i = 0; i < 32; i++) acc[i] = 0.f;
        const float* pr = p + row * 64;
        for (int n = 0; n < nv; n++) {
            float w = pr[n];
            const float* vr = kbuf + n * 64 + half * 32;
#pragma unroll
            for (int i = 0; i < 8; i++) {
                float4 v4 = *reinterpret_cast<const float4*>(&vr[i * 4]);
                acc[i * 4 + 0] += w * v4.x; acc[i * 4 + 1] += w * v4.y;
                acc[i * 4 + 2] += w * v4.z; acc[i * 4 + 3] += w * v4.w;
            }
        }
        float* op = g_ocmp + ((size_t)t * H_ + g * HG + hh) * DV + half * 32;
#pragma unroll
        for (int i = 0; i < 8; i++)
            *reinterpret_cast<float4*>(&op[i * 4]) =
                make_float4(acc[i * 4], acc[i * 4 + 1], acc[i * 4 + 2], acc[i * 4 + 3]);
    }
}

// ---------------- selection branch ----------------
__global__ void sel_kernel2() {
    extern __shared__ float sm[];
    float* kbuf = sm;
    float* p    = sm + 256 * 64;
    float* qs   = p + 16 * 256;
    __shared__ int sidx[NSEL];
    const int t = blockIdx.x, g = blockIdx.y, tid = threadIdx.x;

    if (tid < NSEL) sidx[tid] = g_selidx[(t * G_ + g) * NSEL + tid];
    for (int i = tid; i < HG * DQK / 4; i += 256) {
        int hh = i >> 4, d4 = (i & 15) << 2;
        *reinterpret_cast<float4*>(&qs[hh * 64 + d4]) =
            *reinterpret_cast<const float4*>(g_qkvw + (size_t)t * OUTD + OQ + (g * HG + hh) * DQK + d4);
    }
    __syncthreads();

    for (int i = tid; i < NSEL * BLK * DQK / 4; i += 256) {
        int c = i >> 9, r = (i >> 4) & 31, d4 = (i & 15) << 2;
        int rowg = sidx[c] * BLK + r;
        *reinterpret_cast<float4*>(&kbuf[(c * 32 + r) * 64 + d4]) =
            *reinterpret_cast<const float4*>(g_qkvw + (size_t)rowg * OUTD + OK_ + g * DQK + d4);
    }
    __syncthreads();

    const int hh = tid >> 4, rb = tid & 15;
    {
        float4 q[16];
#pragma unroll
        for (int i = 0; i < 16; i++) q[i] = *reinterpret_cast<float4*>(&qs[hh * 64 + i * 4]);
        for (int k = 0; k < 16; k++) {
            int r = rb + k * 16;
            int pos = sidx[r >> 5] * BLK + (r & 31);
            float s = NEGI;
            if (pos <= t) {
                float a = 0.f;
#pragma unroll
                for (int i = 0; i < 16; i++) {
                    float4 kv = *reinterpret_cast<float4*>(&kbuf[r * 64 + i * 4]);
                    a += q[i].x * kv.x + q[i].y * kv.y + q[i].z * kv.z + q[i].w * kv.w;
                }
                s = a * SCALE;
            }
            p[hh * 256 + r] = s;
        }
    }
    __syncthreads();

    for (int i = tid; i < NSEL * BLK * DV / 4; i += 256) {
        int c = i >> 9, r = (i >> 4) & 31, d4 = (i & 15) << 2;
        int rowg = sidx[c] * BLK + r;
        *reinterpret_cast<float4*>(&kbuf[(c * 32 + r) * 64 + d4]) =
            *reinterpret_cast<const float4*>(g_qkvw + (size_t)rowg * OUTD + OV + g * DV + d4);
    }
    {
        int wid = tid >> 5, lane = tid & 31;
#pragma unroll
        for (int rr = 0; rr < 2; rr++) {
            float* pr = p + (wid * 2 + rr) * 256;
            float v[8];
            float m = NEGI;
#pragma unroll
            for (int i = 0; i < 8; i++) { v[i] = pr[i * 32 + lane]; m = fmaxf(m, v[i]); }
#pragma unroll
            for (int off = 16; off; off >>= 1) m = fmaxf(m, __shfl_xor_sync(0xffffffffu, m, off));
            float s = 0.f;
#pragma unroll
            for (int i = 0; i < 8; i++) { v[i] = __expf(v[i] - m); s += v[i]; }
#pragma unroll
            for (int off = 16; off; off >>= 1) s += __shfl_xor_sync(0xffffffffu, s, off);
            float inv = 1.f / s;
#pragma unroll
            for (int i = 0; i < 8; i++) pr[i * 32 + lane] = v[i] * inv;
        }
    }
    __syncthreads();

    {
        const int d0 = (tid & 15) << 2;
        const float* pr = p + hh * 256;
        float4 acc = make_float4(0.f, 0.f, 0.f, 0.f);
        for (int r = 0; r < 256; r++) {
            float w = pr[r];
            float4 v4 = *reinterpret_cast<float4*>(&kbuf[r * 64 + d0]);
            acc.x += w * v4.x; acc.y += w * v4.y; acc.z += w * v4.z; acc.w += w * v4.w;
        }
        *reinterpret_cast<float4*>(g_osel + ((size_t)t * H_ + g * HG + hh) * DV + d0) = acc;
    }
}

// ---------------- sliding-window branch ----------------
__global__ void win_kernel2() {
    extern __shared__ float sm[];
    float* kbuf = sm;
    float* p    = sm + 256 * 64;
    float* qs   = p + 16 * 256;
    const int t = blockIdx.x, g = blockIdx.y, tid = threadIdx.x;
    const int w0 = t - (WINSZ - 1);

    for (int i = tid; i < HG * DQK / 4; i += 256) {
        int hh = i >> 4, d4 = (i & 15) << 2;
        *reinterpret_cast<float4*>(&qs[hh * 64 + d4]) =
            *reinterpret_cast<const float4*>(g_qkvw + (size_t)t * OUTD + OQ + (g * HG + hh) * DQK + d4);
    }
    for (int i = tid; i < WINSZ * DQK / 4; i += 256) {
        int r = i >> 4, d4 = (i & 15) << 2;
        int pos = w0 + r;
        int rc = pos < 0 ? 0 : pos;
        *reinterpret_cast<float4*>(&kbuf[r * 64 + d4]) =
            *reinterpret_cast<const float4*>(g_qkvw + (size_t)rc * OUTD + OK_ + g * DQK + d4);
    }
    __syncthreads();

    const int hh = tid >> 4, rb = tid & 15;
    {
        float4 q[16];
#pragma unroll
        for (int i = 0; i < 16; i++) q[i] = *reinterpret_cast<float4*>(&qs[hh * 64 + i * 4]);
        for (int k = 0; k < 16; k++) {
            int r = rb + k * 16;
            float s = NEGI;
            if (w0 + r >= 0) {
                float a = 0.f;
#pragma unroll
                for (int i = 0; i < 16; i++) {
                    float4 kv = *reinterpret_cast<float4*>(&kbuf[r * 64 + i * 4]);
                    a += q[i].x * kv.x + q[i].y * kv.y + q[i].z * kv.z + q[i].w * kv.w;
                }
                s = a * SCALE;
            }
            p[hh * 256 + r] = s;
        }
    }
    __syncthreads();

    for (int i = tid; i < WINSZ * DV / 4; i += 256) {
        int r = i >> 4, d4 = (i & 15) << 2;
        int pos = w0 + r;
        int rc = pos < 0 ? 0 : pos;
        *reinterpret_cast<float4*>(&kbuf[r * 64 + d4]) =
            *reinterpret_cast<const float4*>(g_qkvw + (size_t)rc * OUTD + OV + g * DV + d4);
    }
    {
        int wid = tid >> 5, lane = tid & 31;
#pragma unroll
        for (int rr = 0; rr < 2; rr++) {
            float* pr = p + (wid * 2 + rr) * 256;
            float v[8];
            float m = NEGI;
#pragma unroll
            for (int i = 0; i < 8; i++) { v[i] = pr[i * 32 + lane]; m = fmaxf(m, v[i]); }
#pragma unroll
            for (int off = 16; off; off >>= 1) m = fmaxf(m, __shfl_xor_sync(0xffffffffu, m, off));
            float s = 0.f;
#pragma unroll
            for (int i = 0; i < 8; i++) { v[i] = __expf(v[i] - m); s += v[i]; }
#pragma unroll
            for (int off = 16; off; off >>= 1) s += __shfl_xor_sync(0xffffffffu, s, off);
            float inv = 1.f / s;
#pragma unroll
            for (int i = 0; i < 8; i++) pr[i * 32 + lane] = v[i] * inv;
        }
    }
    __syncthreads();

    {
        const int d0 = (tid & 15) << 2;
        const float* pr = p + hh * 256;
        float4 acc = make_float4(0.f, 0.f, 0.f, 0.f);
        for (int r = 0; r < 256; r++) {
            float w = pr[r];
            float4 v4 = *reinterpret_cast<float4*>(&kbuf[r * 64 + d0]);
            acc.x += w * v4.x; acc.y += w * v4.y; acc.z += w * v4.z; acc.w += w * v4.w;
        }
        *reinterpret_cast<float4*>(g_owin + ((size_t)t * H_ + g * HG + hh) * DV + d0) = acc;
    }
}

// ---------------- gated combine ----------------
__global__ void combine_kernel() {
    int idx = blockIdx.x * blockDim.x + threadIdx.x;
    if (idx >= T_ * H_ * DV) return;
    int h = (idx >> 6) & 31;
    int t = idx >> 11;
    const float* wrow = g_qkvw + (size_t)t * OUTD + OW + h * 3;
    float g0 = 1.f / (1.f + __expf(-wrow[0]));
    float g1 = 1.f / (1.f + __expf(-wrow[1]));
    float g2 = 1.f / (1.f + __expf(-wrow[2]));
    g_ocomb[idx] = g0 * g_ocmp[idx] + g1 * g_osel[idx] + g2 * g_owin[idx];
}

// ---------------- launch ----------------
extern "C" void kernel_launch(void* const* d_in, const int* in_sizes, int n_in,
                              void* d_out, int out_size) {
    const float* x    = (const float*)d_in[0];
    const float* cosp = (const float*)d_in[1];
    const float* sinp = (const float*)d_in[2];
    const float* wqkv = (const float*)d_in[3];
    const float* ow   = (const float*)d_in[4];
    float* out = (float*)d_out;

    float *qkvw_p, *ocomb_p;
    cudaGetSymbolAddress((void**)&qkvw_p, g_qkvw);
    cudaGetSymbolAddress((void**)&ocomb_p, g_ocomb);

    const int CMP_SMEM = (64 * 64 + TT * 16 * 64 + TT * 64) * 4;
    const int SW_SMEM  = (256 * 64 + 16 * 256 + 16 * 64) * 4;
    cudaFuncSetAttribute((const void*)gemm_bf16x3, cudaFuncAttributeMaxDynamicSharedMemorySize, GEMM_SMEM);
    cudaFuncSetAttribute((const void*)cmp_kernel2, cudaFuncAttributeMaxDynamicSharedMemorySize, CMP_SMEM);
    cudaFuncSetAttribute((const void*)sel_kernel2, cudaFuncAttributeMaxDynamicSharedMemorySize, SW_SMEM);
    cudaFuncSetAttribute((const void*)win_kernel2, cudaFuncAttributeMaxDynamicSharedMemorySize, SW_SMEM);

    dim3 g1((OUTD + 127) / 128, T_ / 128);
    gemm_bf16x3<<<g1, 256, GEMM_SMEM>>>(x, wqkv, qkvw_p, T_, OUTD, HID);

    rope_kernel<<<T_, 256>>>(cosp, sinp);
    pool_kernel<<<(NB * G_ * DQK + 255) / 256, 256>>>();

    dim3 gc(T_ / TT, G_);
    cmp_kernel2<<<gc, 256, CMP_SMEM>>>();

    dim3 gt(T_, G_);
    sel_kernel2<<<gt, 256, SW_SMEM>>>();
    win_kernel2<<<gt, 256, SW_SMEM>>>();

    combine_kernel<<<(T_ * H_ * DV + 255) / 256, 256>>>();

    dim3 g2(HID / 128, T_ / 128);
    gemm_bf16x3<<<g2, 256, GEMM_SMEM>>>(ocomb_p, ow, out, T_, HID, HID);
}

// round 6
// speedup vs baseline: 1.6521x; 1.0130x over previous
#include <cuda_runtime.h>
#include <cuda_bf16.h>
#include <math.h>
#include <stdint.h>

// ---------------- problem constants ----------------
namespace {
constexpr int T_    = 2048;
constexpr int HID   = 2048;
constexpr int H_    = 32;
constexpr int HKV   = 2;
constexpr int DQK   = 64;
constexpr int DV    = 64;
constexpr int G_    = 2;
constexpr int HG    = 16;
constexpr int BLK   = 32;
constexpr int NSEL  = 8;
constexpr int WINSZ = 256;
constexpr int NB    = 64;
constexpr int OUTD  = 2400;
constexpr int OQ = 0;
constexpr int OK_ = 2048;
constexpr int OV  = 2176;
constexpr int OW  = 2304;
constexpr float SCALE = 0.125f;
constexpr float NEGI  = -1e30f;
constexpr int TT = 8;

// GEMM tiling
constexpr int STG  = 3;
constexpr int ASTR = 40;                 // 32 + 8 pad (bf16)
constexpr int BSTR = 136;                // 128 + 8 pad
constexpr int ASZB = 128 * ASTR * 2;     // 10240 B / stage
constexpr int BSZB = 32 * BSTR * 2;      // 8704 B / stage
constexpr int GEMM_SMEM = STG * (ASZB + BSZB);   // 56832 B
}

// ---------------- scratch ----------------
__device__ float g_qkvw[(size_t)T_ * OUTD];
__device__ float g_kcmp[NB * G_ * DQK];
__device__ float g_vcmp[NB * G_ * DV];
__device__ float g_ocmp[(size_t)T_ * H_ * DV];
__device__ float g_osel[(size_t)T_ * H_ * DV];
__device__ float g_owin[(size_t)T_ * H_ * DV];
__device__ int   g_selidx[T_ * G_ * NSEL];
// bf16 hi/lo split buffers
__device__ __nv_bfloat16 g_xh[(size_t)T_ * HID];
__device__ __nv_bfloat16 g_xl[(size_t)T_ * HID];
__device__ __nv_bfloat16 g_wh[(size_t)HID * OUTD];
__device__ __nv_bfloat16 g_wl[(size_t)HID * OUTD];
__device__ __nv_bfloat16 g_owh[(size_t)H_ * DV * HID];
__device__ __nv_bfloat16 g_owl[(size_t)H_ * DV * HID];
__device__ __nv_bfloat16 g_och[(size_t)T_ * H_ * DV];
__device__ __nv_bfloat16 g_ocl[(size_t)T_ * H_ * DV];

// ---------------- helpers ----------------
__device__ __forceinline__ uint32_t smem_u32(const void* p) {
    return (uint32_t)__cvta_generic_to_shared(p);
}
__device__ __forceinline__ void ldsm_x4(uint32_t addr, uint32_t& r0, uint32_t& r1,
                                        uint32_t& r2, uint32_t& r3) {
    asm volatile("ldmatrix.sync.aligned.m8n8.x4.shared.b16 {%0,%1,%2,%3}, [%4];"
                 : "=r"(r0), "=r"(r1), "=r"(r2), "=r"(r3) : "r"(addr));
}
__device__ __forceinline__ void ldsm_x2t(uint32_t addr, uint32_t& r0, uint32_t& r1) {
    asm volatile("ldmatrix.sync.aligned.m8n8.x2.trans.shared.b16 {%0,%1}, [%2];"
                 : "=r"(r0), "=r"(r1) : "r"(addr));
}
__device__ __forceinline__ void mma_bf16(float* c, const uint32_t* a, const uint32_t* b) {
    asm volatile(
        "mma.sync.aligned.m16n8k16.row.col.f32.bf16.bf16.f32 "
        "{%0,%1,%2,%3}, {%4,%5,%6,%7}, {%8,%9}, {%0,%1,%2,%3};"
        : "+f"(c[0]), "+f"(c[1]), "+f"(c[2]), "+f"(c[3])
        : "r"(a[0]), "r"(a[1]), "r"(a[2]), "r"(a[3]), "r"(b[0]), "r"(b[1]));
}
__device__ __forceinline__ void cp16(uint32_t dst, const void* src, bool pred) {
    int sz = pred ? 16 : 0;
    asm volatile("cp.async.cg.shared.global [%0], [%1], 16, %2;"
                 :: "r"(dst), "l"(src), "r"(sz));
}
__device__ __forceinline__ void cp_commit() { asm volatile("cp.async.commit_group;"); }
template <int N> __device__ __forceinline__ void cp_wait() {
    asm volatile("cp.async.wait_group %0;" :: "n"(N));
}
__device__ __forceinline__ void split2(float x, float y, uint32_t& hi, uint32_t& lo) {
    __nv_bfloat16 xh = __float2bfloat16(x);
    __nv_bfloat16 yh = __float2bfloat16(y);
    __nv_bfloat16 xl = __float2bfloat16(x - __bfloat162float(xh));
    __nv_bfloat16 yl = __float2bfloat16(y - __bfloat162float(yh));
    __nv_bfloat162 h2 = __nv_bfloat162(xh, yh);
    __nv_bfloat162 l2 = __nv_bfloat162(xl, yl);
    hi = *reinterpret_cast<uint32_t*>(&h2);
    lo = *reinterpret_cast<uint32_t*>(&l2);
}

// ---------------- fp32 -> bf16 hi/lo split ----------------
__global__ void split_kernel(const float* __restrict__ src,
                             __nv_bfloat16* __restrict__ hi,
                             __nv_bfloat16* __restrict__ lo, int n2) {
    int i = blockIdx.x * blockDim.x + threadIdx.x;   // pair index
    if (i >= n2) return;
    float2 v = *reinterpret_cast<const float2*>(src + 2 * (size_t)i);
    uint32_t h, l;
    split2(v.x, v.y, h, l);
    reinterpret_cast<uint32_t*>(hi)[i] = h;
    reinterpret_cast<uint32_t*>(lo)[i] = l;
}

// ---------------- K-tripled bf16 GEMM ----------------
// C[M,N] = Ah@Bh + Al@Bh + Ah@Bl  (fp32 accum), i.e. fp32-GEMM to ~1e-5.
// block 128x128, BK=32 over K'=3K, 256 threads, 3-stage cp.async pipeline.
__global__ void __launch_bounds__(256)
gemm_k3(const __nv_bfloat16* __restrict__ Ah, const __nv_bfloat16* __restrict__ Al,
        const __nv_bfloat16* __restrict__ Bh, const __nv_bfloat16* __restrict__ Bl,
        float* __restrict__ C, int M, int N, int K) {
    extern __shared__ char smraw[];
    const uint32_t aBase = smem_u32(smraw);
    const uint32_t bBase = aBase + STG * ASZB;

    const int tid  = threadIdx.x;
    const int lane = tid & 31;
    const int wid  = tid >> 5;
    const int wm   = wid & 1;
    const int wn   = wid >> 1;
    const int bx = blockIdx.x, by = blockIdx.y;
    const int cColBase = bx * 128;
    const int nIter = 3 * K / 32;

    // cp.async chunk coords (2 chunks each of A and B per thread)
    const int aRow0 = (tid * 2) >> 2,        aC0 = ((tid * 2) & 3) * 8;
    const int aRow1 = (tid * 2 + 1) >> 2,    aC1 = ((tid * 2 + 1) & 3) * 8;
    const int bRow0 = (tid * 2) >> 4,        bC0 = ((tid * 2) & 15) * 8;
    const int bRow1 = (tid * 2 + 1) >> 4,    bC1 = ((tid * 2 + 1) & 15) * 8;
    const bool bOk0 = (cColBase + bC0) < N;
    const bool bOk1 = (cColBase + bC1) < N;

    auto issue = [&](int it) {
        const int kIdx = it * 32;
        const int seg  = (kIdx >= 2 * K) ? 2 : (kIdx >= K ? 1 : 0);
        const __nv_bfloat16* aSrc = (seg == 1) ? Al : Ah;
        const __nv_bfloat16* bSrc = (seg == 2) ? Bl : Bh;
        const int ak = kIdx - seg * K;   // kIdx mod K for every segment
        const int bk = ak;
        const int st = it % STG;
        uint32_t ad = aBase + st * ASZB;
        uint32_t bd = bBase + st * BSZB;
        cp16(ad + (aRow0 * ASTR + aC0) * 2,
             aSrc + (size_t)(by * 128 + aRow0) * K + ak + aC0, true);
        cp16(ad + (aRow1 * ASTR + aC1) * 2,
             aSrc + (size_t)(by * 128 + aRow1) * K + ak + aC1, true);
        cp16(bd + (bRow0 * BSTR + bC0) * 2,
             bSrc + (size_t)(bk + bRow0) * N + cColBase + bC0, bOk0);
        cp16(bd + (bRow1 * BSTR + bC1) * 2,
             bSrc + (size_t)(bk + bRow1) * N + cColBase + bC1, bOk1);
    };

    float acc[4][4][4];
#pragma unroll
    for (int i = 0; i < 4; i++)
#pragma unroll
        for (int j = 0; j < 4; j++)
#pragma unroll
            for (int r = 0; r < 4; r++) acc[i][j][r] = 0.f;

    const int aLaneRow = wm * 64 + (lane & 15);
    const int aLaneK   = (lane >> 4) << 3;
    const int bLaneK   = lane & 15;
    const int bLaneCol = wn * 32;

    // prologue: stages 0..STG-2
#pragma unroll
    for (int s = 0; s < STG - 1; s++) { issue(s); cp_commit(); }
    cp_wait<STG - 2>();
    __syncthreads();

    for (int it = 0; it < nIter; it++) {
        const int cur = it % STG;
        if (it + STG - 1 < nIter) issue(it + STG - 1);
        cp_commit();

        const uint32_t aB = aBase + cur * ASZB;
        const uint32_t bB = bBase + cur * BSZB;
#pragma unroll
        for (int kk = 0; kk < 32; kk += 16) {
            uint32_t a[4][4], b[4][2];
#pragma unroll
            for (int mt = 0; mt < 4; mt++) {
                uint32_t off = ((aLaneRow + mt * 16) * ASTR + kk + aLaneK) * 2;
                ldsm_x4(aB + off, a[mt][0], a[mt][1], a[mt][2], a[mt][3]);
            }
#pragma unroll
            for (int nt = 0; nt < 4; nt++) {
                uint32_t off = ((kk + bLaneK) * BSTR + bLaneCol + nt * 8) * 2;
                ldsm_x2t(bB + off, b[nt][0], b[nt][1]);
            }
#pragma unroll
            for (int mt = 0; mt < 4; mt++)
#pragma unroll
                for (int nt = 0; nt < 4; nt++)
                    mma_bf16(acc[mt][nt], a[mt], b[nt]);
        }
        cp_wait<STG - 2>();
        __syncthreads();
    }

    const int rBase = by * 128 + wm * 64 + (lane >> 2);
    const int cBase = cColBase + wn * 32 + (lane & 3) * 2;
#pragma unroll
    for (int mt = 0; mt < 4; mt++)
#pragma unroll
        for (int nt = 0; nt < 4; nt++) {
            int r0 = rBase + mt * 16;
            int c0 = cBase + nt * 8;
            if (c0 < N) {
                *reinterpret_cast<float2*>(C + (size_t)r0 * N + c0) =
                    make_float2(acc[mt][nt][0], acc[mt][nt][1]);
                *reinterpret_cast<float2*>(C + (size_t)(r0 + 8) * N + c0) =
                    make_float2(acc[mt][nt][2], acc[mt][nt][3]);
            }
        }
}

// ---------------- RoPE ----------------
__global__ void rope_kernel(const float* __restrict__ cosp, const float* __restrict__ sinp) {
    int t = blockIdx.x;
    float* row = g_qkvw + (size_t)t * OUTD;
    for (int i = threadIdx.x; i < (H_ + HKV) * 32; i += blockDim.x) {
        int head = i >> 5, dp = i & 31;
        float* base = (head < H_) ? (row + OQ + head * DQK)
                                  : (row + OK_ + (head - H_) * DQK);
        float x1 = base[dp], x2 = base[dp + 32];
        float c1 = cosp[t * DQK + dp],      s1 = sinp[t * DQK + dp];
        float c2 = cosp[t * DQK + dp + 32], s2 = sinp[t * DQK + dp + 32];
        base[dp]      = x1 * c1 - x2 * s1;
        base[dp + 32] = x2 * c2 + x1 * s2;
    }
}

// ---------------- mean pool ----------------
__global__ void pool_kernel() {
    int idx = blockIdx.x * blockDim.x + threadIdx.x;
    if (idx >= NB * G_ * DQK) return;
    int nb = idx / (G_ * DQK);
    int g  = (idx / DQK) % G_;
    int d  = idx % DQK;
    float sk = 0.f, sv = 0.f;
    for (int i = 0; i < BLK; i++) {
        const float* r = g_qkvw + (size_t)(nb * BLK + i) * OUTD;
        sk += r[OK_ + g * DQK + d];
        sv += r[OV  + g * DV  + d];
    }
    g_kcmp[idx] = sk * (1.f / BLK);
    g_vcmp[idx] = sv * (1.f / BLK);
}

// ---------------- compressed branch + top-k ----------------
__global__ void cmp_kernel2() {
    extern __shared__ float sm[];
    float* kbuf = sm;
    float* p    = sm + 4096;
    float* imp  = p + TT * 16 * 64;
    const int t0 = blockIdx.x * TT;
    const int g  = blockIdx.y;
    const int tid = threadIdx.x;

    for (int i = tid; i < NB * DQK / 4; i += 256) {
        int n = i >> 4, d4 = (i & 15) << 2;
        *reinterpret_cast<float4*>(&kbuf[n * 64 + d4]) =
            *reinterpret_cast<const float4*>(&g_kcmp[(n * G_ + g) * DQK + d4]);
    }
    __syncthreads();

    const int row = tid >> 1;
    const int tt = row >> 4, hh = row & 15;
    const int t = t0 + tt;
    const int half = tid & 1;
    {
        float4 q[16];
        const float4* qp = reinterpret_cast<const float4*>(
            g_qkvw + (size_t)t * OUTD + OQ + (g * HG + hh) * DQK);
#pragma unroll
        for (int i = 0; i < 16; i++) q[i] = qp[i];
        const int nvis = (t + 1) >> 5;
        float* prow = p + row * 64;
        for (int n = half * 32; n < half * 32 + 32; n++) {
            float s = NEGI;
            if (n < nvis) {
                float a = 0.f;
#pragma unroll
                for (int i = 0; i < 16; i++) {
                    float4 kv = *reinterpret_cast<float4*>(&kbuf[n * 64 + i * 4]);
                    a += q[i].x * kv.x + q[i].y * kv.y + q[i].z * kv.z + q[i].w * kv.w;
                }
                s = a * SCALE;
            }
            prow[n] = s;
        }
    }
    __syncthreads();

    for (int i = tid; i < NB * DV / 4; i += 256) {
        int n = i >> 4, d4 = (i & 15) << 2;
        *reinterpret_cast<float4*>(&kbuf[n * 64 + d4]) =
            *reinterpret_cast<const float4*>(&g_vcmp[(n * G_ + g) * DV + d4]);
    }
    if (tid < 128) {
        float* pr = p + tid * 64;
        int tloc = t0 + (tid >> 4);
        int nv = (tloc + 1) >> 5;
        if (nv == 0) {
            for (int n = 0; n < 64; n++) pr[n] = 0.f;
        } else {
            float m = NEGI;
            for (int n = 0; n < 64; n++) m = fmaxf(m, pr[n]);
            float s = 0.f;
            for (int n = 0; n < 64; n++) { float e = __expf(pr[n] - m); pr[n] = e; s += e; }
            float inv = 1.f / s;
            for (int n = 0; n < 64; n++) pr[n] *= inv;
        }
    }
    __syncthreads();

    for (int i = tid; i < TT * NB; i += 256) {
        int tti = i >> 6, n = i & 63;
        int tloc = t0 + tti, cur = tloc >> 5;
        float v;
        if (n > cur) v = NEGI;
        else {
            v = 0.f;
            for (int h2 = 0; h2 < 16; h2++) v += p[(tti * 16 + h2) * 64 + n];
            if (n == 0)   v += 1e4f;
            if (n == cur) v += 1e4f;
        }
        imp[i] = v;
    }
    __syncthreads();

    {
        int wid = tid >> 5, lane = tid & 31;
        if (wid < TT) {
            float v0 = imp[wid * 64 + lane];
            float v1 = imp[wid * 64 + 32 + lane];
            int* outp = g_selidx + ((t0 + wid) * G_ + g) * NSEL;
            for (int j = 0; j < NSEL; j++) {
                float bv = v0; int bi = lane;
                if (v1 > bv) { bv = v1; bi = lane + 32; }
#pragma unroll
                for (int off = 16; off; off >>= 1) {
                    float ov = __shfl_xor_sync(0xffffffffu, bv, off);
                    int   oi = __shfl_xor_sync(0xffffffffu, bi, off);
                    if (ov > bv || (ov == bv && oi < bi)) { bv = ov; bi = oi; }
                }
                if (lane == 0) outp[j] = bi;
                if (bi == lane)      v0 = -2e30f;
                if (bi == lane + 32) v1 = -2e30f;
            }
        }
    }

    {
        const int nv = (t + 1) >> 5;
        float acc[32];
#pragma unroll
        for (int i = 0; i < 32; i++) acc[i] = 0.f;
        const float* pr = p + row * 64;
        for (int n = 0; n < nv; n++) {
            float w = pr[n];
            const float* vr = kbuf + n * 64 + half * 32;
#pragma unroll
            for (int i = 0; i < 8; i++) {
                float4 v4 = *reinterpret_cast<const float4*>(&vr[i * 4]);
                acc[i * 4 + 0] += w * v4.x; acc[i * 4 + 1] += w * v4.y;
                acc[i * 4 + 2] += w * v4.z; acc[i * 4 + 3] += w * v4.w;
            }
        }
        float* op = g_ocmp + ((size_t)t * H_ + g * HG + hh) * DV + half * 32;
#pragma unroll
        for (int i = 0; i < 8; i++)
            *reinterpret_cast<float4*>(&op[i * 4]) =
                make_float4(acc[i * 4], acc[i * 4 + 1], acc[i * 4 + 2], acc[i * 4 + 3]);
    }
}

// ---------------- selection branch ----------------
__global__ void sel_kernel2() {
    extern __shared__ float sm[];
    float* kbuf = sm;
    float* p    = sm + 256 * 64;
    float* qs   = p + 16 * 256;
    __shared__ int sidx[NSEL];
    const int t = blockIdx.x, g = blockIdx.y, tid = threadIdx.x;

    if (tid < NSEL) sidx[tid] = g_selidx[(t * G_ + g) * NSEL + tid];
    for (int i = tid; i < HG * DQK / 4; i += 256) {
        int hh = i >> 4, d4 = (i & 15) << 2;
        *reinterpret_cast<float4*>(&qs[hh * 64 + d4]) =
            *reinterpret_cast<const float4*>(g_qkvw + (size_t)t * OUTD + OQ + (g * HG + hh) * DQK + d4);
    }
    __syncthreads();

    for (int i = tid; i < NSEL * BLK * DQK / 4; i += 256) {
        int c = i >> 9, r = (i >> 4) & 31, d4 = (i & 15) << 2;
        int rowg = sidx[c] * BLK + r;
        *reinterpret_cast<float4*>(&kbuf[(c * 32 + r) * 64 + d4]) =
            *reinterpret_cast<const float4*>(g_qkvw + (size_t)rowg * OUTD + OK_ + g * DQK + d4);
    }
    __syncthreads();

    const int hh = tid >> 4, rb = tid & 15;
    {
        float4 q[16];
#pragma unroll
        for (int i = 0; i < 16; i++) q[i] = *reinterpret_cast<float4*>(&qs[hh * 64 + i * 4]);
        for (int k = 0; k < 16; k++) {
            int r = rb + k * 16;
            int pos = sidx[r >> 5] * BLK + (r & 31);
            float s = NEGI;
            if (pos <= t) {
                float a = 0.f;
#pragma unroll
                for (int i = 0; i < 16; i++) {
                    float4 kv = *reinterpret_cast<float4*>(&kbuf[r * 64 + i * 4]);
                    a += q[i].x * kv.x + q[i].y * kv.y + q[i].z * kv.z + q[i].w * kv.w;
                }
                s = a * SCALE;
            }
            p[hh * 256 + r] = s;
        }
    }
    __syncthreads();

    for (int i = tid; i < NSEL * BLK * DV / 4; i += 256) {
        int c = i >> 9, r = (i >> 4) & 31, d4 = (i & 15) << 2;
        int rowg = sidx[c] * BLK + r;
        *reinterpret_cast<float4*>(&kbuf[(c * 32 + r) * 64 + d4]) =
            *reinterpret_cast<const float4*>(g_qkvw + (size_t)rowg * OUTD + OV + g * DV + d4);
    }
    {
        int wid = tid >> 5, lane = tid & 31;
#pragma unroll
        for (int rr = 0; rr < 2; rr++) {
            float* pr = p + (wid * 2 + rr) * 256;
            float v[8];
            float m = NEGI;
#pragma unroll
            for (int i = 0; i < 8; i++) { v[i] = pr[i * 32 + lane]; m = fmaxf(m, v[i]); }
#pragma unroll
            for (int off = 16; off; off >>= 1) m = fmaxf(m, __shfl_xor_sync(0xffffffffu, m, off));
            float s = 0.f;
#pragma unroll
            for (int i = 0; i < 8; i++) { v[i] = __expf(v[i] - m); s += v[i]; }
#pragma unroll
            for (int off = 16; off; off >>= 1) s += __shfl_xor_sync(0xffffffffu, s, off);
            float inv = 1.f / s;
#pragma unroll
            for (int i = 0; i < 8; i++) pr[i * 32 + lane] = v[i] * inv;
        }
    }
    __syncthreads();

    {
        const int d0 = (tid & 15) << 2;
        const float* pr = p + hh * 256;
        float4 acc = make_float4(0.f, 0.f, 0.f, 0.f);
        for (int r = 0; r < 256; r++) {
            float w = pr[r];
            float4 v4 = *reinterpret_cast<float4*>(&kbuf[r * 64 + d0]);
            acc.x += w * v4.x; acc.y += w * v4.y; acc.z += w * v4.z; acc.w += w * v4.w;
        }
        *reinterpret_cast<float4*>(g_osel + ((size_t)t * H_ + g * HG + hh) * DV + d0) = acc;
    }
}

// ---------------- sliding-window branch ----------------
__global__ void win_kernel2() {
    extern __shared__ float sm[];
    float* kbuf = sm;
    float* p    = sm + 256 * 64;
    float* qs   = p + 16 * 256;
    const int t = blockIdx.x, g = blockIdx.y, tid = threadIdx.x;
    const int w0 = t - (WINSZ - 1);

    for (int i = tid; i < HG * DQK / 4; i += 256) {
        int hh = i >> 4, d4 = (i & 15) << 2;
        *reinterpret_cast<float4*>(&qs[hh * 64 + d4]) =
            *reinterpret_cast<const float4*>(g_qkvw + (size_t)t * OUTD + OQ + (g * HG + hh) * DQK + d4);
    }
    for (int i = tid; i < WINSZ * DQK / 4; i += 256) {
        int r = i >> 4, d4 = (i & 15) << 2;
        int pos = w0 + r;
        int rc = pos < 0 ? 0 : pos;
        *reinterpret_cast<float4*>(&kbuf[r * 64 + d4]) =
            *reinterpret_cast<const float4*>(g_qkvw + (size_t)rc * OUTD + OK_ + g * DQK + d4);
    }
    __syncthreads();

    const int hh = tid >> 4, rb = tid & 15;
    {
        float4 q[16];
#pragma unroll
        for (int i = 0; i < 16; i++) q[i] = *reinterpret_cast<float4*>(&qs[hh * 64 + i * 4]);
        for (int k = 0; k < 16; k++) {
            int r = rb + k * 16;
            float s = NEGI;
            if (w0 + r >= 0) {
                float a = 0.f;
#pragma unroll
                for (int i = 0; i < 16; i++) {
                    float4 kv = *reinterpret_cast<float4*>(&kbuf[r * 64 + i * 4]);
                    a += q[i].x * kv.x + q[i].y * kv.y + q[i].z * kv.z + q[i].w * kv.w;
                }
                s = a * SCALE;
            }
            p[hh * 256 + r] = s;
        }
    }
    __syncthreads();

    for (int i = tid; i < WINSZ * DV / 4; i += 256) {
        int r = i >> 4, d4 = (i & 15) << 2;
        int pos = w0 + r;
        int rc = pos < 0 ? 0 : pos;
        *reinterpret_cast<float4*>(&kbuf[r * 64 + d4]) =
            *reinterpret_cast<const float4*>(g_qkvw + (size_t)rc * OUTD + OV + g * DV + d4);
    }
    {
        int wid = tid >> 5, lane = tid & 31;
#pragma unroll
        for (int rr = 0; rr < 2; rr++) {
            float* pr = p + (wid * 2 + rr) * 256;
            float v[8];
            float m = NEGI;
#pragma unroll
            for (int i = 0; i < 8; i++) { v[i] = pr[i * 32 + lane]; m = fmaxf(m, v[i]); }
#pragma unroll
            for (int off = 16; off; off >>= 1) m = fmaxf(m, __shfl_xor_sync(0xffffffffu, m, off));
            float s = 0.f;
#pragma unroll
            for (int i = 0; i < 8; i++) { v[i] = __expf(v[i] - m); s += v[i]; }
#pragma unroll
            for (int off = 16; off; off >>= 1) s += __shfl_xor_sync(0xffffffffu, s, off);
            float inv = 1.f / s;
#pragma unroll
            for (int i = 0; i < 8; i++) pr[i * 32 + lane] = v[i] * inv;
        }
    }
    __syncthreads();

    {
        const int d0 = (tid & 15) << 2;
        const float* pr = p + hh * 256;
        float4 acc = make_float4(0.f, 0.f, 0.f, 0.f);
        for (int r = 0; r < 256; r++) {
            float w = pr[r];
            float4 v4 = *reinterpret_cast<float4*>(&kbuf[r * 64 + d0]);
            acc.x += w * v4.x; acc.y += w * v4.y; acc.z += w * v4.z; acc.w += w * v4.w;
        }
        *reinterpret_cast<float4*>(g_owin + ((size_t)t * H_ + g * HG + hh) * DV + d0) = acc;
    }
}

// ---------------- gated combine + bf16 split (for GEMM2 A) ----------------
__global__ void combine_split_kernel() {
    int i = blockIdx.x * blockDim.x + threadIdx.x;     // pair index
    if (i >= T_ * H_ * DV / 2) return;
    int e = 2 * i;
    int h = (e >> 6) & 31;
    int t = e >> 11;
    const float* wrow = g_qkvw + (size_t)t * OUTD + OW + h * 3;
    float g0 = 1.f / (1.f + __expf(-wrow[0]));
    float g1 = 1.f / (1.f + __expf(-wrow[1]));
    float g2 = 1.f / (1.f + __expf(-wrow[2]));
    float o0 = g0 * g_ocmp[e]     + g1 * g_osel[e]     + g2 * g_owin[e];
    float o1 = g0 * g_ocmp[e + 1] + g1 * g_osel[e + 1] + g2 * g_owin[e + 1];
    uint32_t hi, lo;
    split2(o0, o1, hi, lo);
    reinterpret_cast<uint32_t*>(g_och)[i] = hi;
    reinterpret_cast<uint32_t*>(g_ocl)[i] = lo;
}

// ---------------- launch ----------------
extern "C" void kernel_launch(void* const* d_in, const int* in_sizes, int n_in,
                              void* d_out, int out_size) {
    const float* x    = (const float*)d_in[0];
    const float* cosp = (const float*)d_in[1];
    const float* sinp = (const float*)d_in[2];
    const float* wqkv = (const float*)d_in[3];
    const float* ow   = (const float*)d_in[4];
    float* out = (float*)d_out;

    float* qkvw_p;
    cudaGetSymbolAddress((void**)&qkvw_p, g_qkvw);
    __nv_bfloat16 *xh, *xl, *wh, *wl, *owh, *owl, *och, *ocl;
    cudaGetSymbolAddress((void**)&xh, g_xh);   cudaGetSymbolAddress((void**)&xl, g_xl);
    cudaGetSymbolAddress((void**)&wh, g_wh);   cudaGetSymbolAddress((void**)&wl, g_wl);
    cudaGetSymbolAddress((void**)&owh, g_owh); cudaGetSymbolAddress((void**)&owl, g_owl);
    cudaGetSymbolAddress((void**)&och, g_och); cudaGetSymbolAddress((void**)&ocl, g_ocl);

    const int CMP_SMEM = (64 * 64 + TT * 16 * 64 + TT * 64) * 4;
    const int SW_SMEM  = (256 * 64 + 16 * 256 + 16 * 64) * 4;
    cudaFuncSetAttribute((const void*)gemm_k3, cudaFuncAttributeMaxDynamicSharedMemorySize, GEMM_SMEM);
    cudaFuncSetAttribute((const void*)cmp_kernel2, cudaFuncAttributeMaxDynamicSharedMemorySize, CMP_SMEM);
    cudaFuncSetAttribute((const void*)sel_kernel2, cudaFuncAttributeMaxDynamicSharedMemorySize, SW_SMEM);
    cudaFuncSetAttribute((const void*)win_kernel2, cudaFuncAttributeMaxDynamicSharedMemorySize, SW_SMEM);

    // splits
    split_kernel<<<(T_ * HID / 2 + 255) / 256, 256>>>(x, xh, xl, T_ * HID / 2);
    split_kernel<<<(HID * OUTD / 2 + 255) / 256, 256>>>(wqkv, wh, wl, HID * OUTD / 2);
    split_kernel<<<(H_ * DV * HID / 2 + 255) / 256, 256>>>(ow, owh, owl, H_ * DV * HID / 2);

    // GEMM1: qkvw = x @ wqkv
    dim3 g1((OUTD + 127) / 128, T_ / 128);
    gemm_k3<<<g1, 256, GEMM_SMEM>>>(xh, xl, wh, wl, qkvw_p, T_, OUTD, HID);

    rope_kernel<<<T_, 256>>>(cosp, sinp);
    pool_kernel<<<(NB * G_ * DQK + 255) / 256, 256>>>();

    dim3 gc(T_ / TT, G_);
    cmp_kernel2<<<gc, 256, CMP_SMEM>>>();

    dim3 gt(T_, G_);
    sel_kernel2<<<gt, 256, SW_SMEM>>>();
    win_kernel2<<<gt, 256, SW_SMEM>>>();

    combine_split_kernel<<<(T_ * H_ * DV / 2 + 255) / 256, 256>>>();

    // GEMM2: out = ocomb @ ow
    dim3 g2(HID / 128, T_ / 128);
    gemm_k3<<<g2, 256, GEMM_SMEM>>>(och, ocl, owh, owl, out, T_, HID, HID);
}

// round 8
// speedup vs baseline: 3.5148x; 2.1275x over previous
#include <cuda_runtime.h>
#include <cuda_bf16.h>
#include <math.h>
#include <stdint.h>

// ---------------- problem constants ----------------
namespace {
constexpr int T_    = 2048;
constexpr int HID   = 2048;
constexpr int H_    = 32;
constexpr int HKV   = 2;
constexpr int DQK   = 64;
constexpr int DV    = 64;
constexpr int G_    = 2;
constexpr int HG    = 16;
constexpr int BLK   = 32;
constexpr int NSEL  = 8;
constexpr int WINSZ = 256;
constexpr int NB    = 64;
constexpr int OUTD  = 2400;
constexpr int OQ = 0;
constexpr int OK_ = 2048;
constexpr int OV  = 2176;
constexpr int OW  = 2304;
constexpr float SCALE = 0.125f;
constexpr float NEGI  = -1e30f;
constexpr int TT = 8;
constexpr int KSTR = 68;                 // padded smem row stride (floats) for sel/win

// GEMM tiling
constexpr int STG  = 3;
constexpr int ASTR = 40;
constexpr int BSTR = 136;
constexpr int ASZB = 128 * ASTR * 2;
constexpr int BSZB = 32 * BSTR * 2;
constexpr int GEMM_SMEM = STG * (ASZB + BSZB);
}

// ---------------- scratch ----------------
__device__ float g_qkvw[(size_t)T_ * OUTD];
__device__ float g_kcmp[NB * G_ * DQK];
__device__ float g_vcmp[NB * G_ * DV];
__device__ float g_ocmp[(size_t)T_ * H_ * DV];
__device__ float g_osel[(size_t)T_ * H_ * DV];
__device__ float g_owin[(size_t)T_ * H_ * DV];
__device__ int   g_selidx[T_ * G_ * NSEL];
__device__ __nv_bfloat16 g_xh[(size_t)T_ * HID];
__device__ __nv_bfloat16 g_xl[(size_t)T_ * HID];
__device__ __nv_bfloat16 g_wh[(size_t)HID * OUTD];
__device__ __nv_bfloat16 g_wl[(size_t)HID * OUTD];
__device__ __nv_bfloat16 g_owh[(size_t)H_ * DV * HID];
__device__ __nv_bfloat16 g_owl[(size_t)H_ * DV * HID];
__device__ __nv_bfloat16 g_och[(size_t)T_ * H_ * DV];
__device__ __nv_bfloat16 g_ocl[(size_t)T_ * H_ * DV];

// ---------------- helpers ----------------
__device__ __forceinline__ uint32_t smem_u32(const void* p) {
    return (uint32_t)__cvta_generic_to_shared(p);
}
__device__ __forceinline__ void ldsm_x4(uint32_t addr, uint32_t& r0, uint32_t& r1,
                                        uint32_t& r2, uint32_t& r3) {
    asm volatile("ldmatrix.sync.aligned.m8n8.x4.shared.b16 {%0,%1,%2,%3}, [%4];"
                 : "=r"(r0), "=r"(r1), "=r"(r2), "=r"(r3) : "r"(addr));
}
__device__ __forceinline__ void ldsm_x2t(uint32_t addr, uint32_t& r0, uint32_t& r1) {
    asm volatile("ldmatrix.sync.aligned.m8n8.x2.trans.shared.b16 {%0,%1}, [%2];"
                 : "=r"(r0), "=r"(r1) : "r"(addr));
}
__device__ __forceinline__ void mma_bf16(float* c, const uint32_t* a, const uint32_t* b) {
    asm volatile(
        "mma.sync.aligned.m16n8k16.row.col.f32.bf16.bf16.f32 "
        "{%0,%1,%2,%3}, {%4,%5,%6,%7}, {%8,%9}, {%0,%1,%2,%3};"
        : "+f"(c[0]), "+f"(c[1]), "+f"(c[2]), "+f"(c[3])
        : "r"(a[0]), "r"(a[1]), "r"(a[2]), "r"(a[3]), "r"(b[0]), "r"(b[1]));
}
__device__ __forceinline__ void cp16(uint32_t dst, const void* src, bool pred) {
    int sz = pred ? 16 : 0;
    asm volatile("cp.async.cg.shared.global [%0], [%1], 16, %2;"
                 :: "r"(dst), "l"(src), "r"(sz));
}
__device__ __forceinline__ void cp_commit() { asm volatile("cp.async.commit_group;"); }
template <int N> __device__ __forceinline__ void cp_wait() {
    asm volatile("cp.async.wait_group %0;" :: "n"(N));
}
__device__ __forceinline__ void split2(float x, float y, uint32_t& hi, uint32_t& lo) {
    __nv_bfloat16 xh = __float2bfloat16(x);
    __nv_bfloat16 yh = __float2bfloat16(y);
    __nv_bfloat16 xl = __float2bfloat16(x - __bfloat162float(xh));
    __nv_bfloat16 yl = __float2bfloat16(y - __bfloat162float(yh));
    __nv_bfloat162 h2 = __nv_bfloat162(xh, yh);
    __nv_bfloat162 l2 = __nv_bfloat162(xl, yl);
    hi = *reinterpret_cast<uint32_t*>(&h2);
    lo = *reinterpret_cast<uint32_t*>(&l2);
}

// ---------------- fp32 -> bf16 hi/lo split ----------------
__global__ void split_kernel(const float* __restrict__ src,
                             __nv_bfloat16* __restrict__ hi,
                             __nv_bfloat16* __restrict__ lo, int n2) {
    int i = blockIdx.x * blockDim.x + threadIdx.x;
    if (i >= n2) return;
    float2 v = *reinterpret_cast<const float2*>(src + 2 * (size_t)i);
    uint32_t h, l;
    split2(v.x, v.y, h, l);
    reinterpret_cast<uint32_t*>(hi)[i] = h;
    reinterpret_cast<uint32_t*>(lo)[i] = l;
}

// ---------------- K-tripled bf16 GEMM ----------------
__global__ void __launch_bounds__(256)
gemm_k3(const __nv_bfloat16* __restrict__ Ah, const __nv_bfloat16* __restrict__ Al,
        const __nv_bfloat16* __restrict__ Bh, const __nv_bfloat16* __restrict__ Bl,
        float* __restrict__ C, int M, int N, int K) {
    extern __shared__ char smraw[];
    const uint32_t aBase = smem_u32(smraw);
    const uint32_t bBase = aBase + STG * ASZB;

    const int tid  = threadIdx.x;
    const int lane = tid & 31;
    const int wid  = tid >> 5;
    const int wm   = wid & 1;
    const int wn   = wid >> 1;
    const int bx = blockIdx.x, by = blockIdx.y;
    const int cColBase = bx * 128;
    const int nIter = 3 * K / 32;

    const int aRow0 = (tid * 2) >> 2,        aC0 = ((tid * 2) & 3) * 8;
    const int aRow1 = (tid * 2 + 1) >> 2,    aC1 = ((tid * 2 + 1) & 3) * 8;
    const int bRow0 = (tid * 2) >> 4,        bC0 = ((tid * 2) & 15) * 8;
    const int bRow1 = (tid * 2 + 1) >> 4,    bC1 = ((tid * 2 + 1) & 15) * 8;
    const bool bOk0 = (cColBase + bC0) < N;
    const bool bOk1 = (cColBase + bC1) < N;

    auto issue = [&](int it) {
        const int kIdx = it * 32;
        const int seg  = (kIdx >= 2 * K) ? 2 : (kIdx >= K ? 1 : 0);
        const __nv_bfloat16* aSrc = (seg == 1) ? Al : Ah;
        const __nv_bfloat16* bSrc = (seg == 2) ? Bl : Bh;
        const int ak = kIdx - seg * K;
        const int bk = ak;
        const int st = it % STG;
        uint32_t ad = aBase + st * ASZB;
        uint32_t bd = bBase + st * BSZB;
        cp16(ad + (aRow0 * ASTR + aC0) * 2,
             aSrc + (size_t)(by * 128 + aRow0) * K + ak + aC0, true);
        cp16(ad + (aRow1 * ASTR + aC1) * 2,
             aSrc + (size_t)(by * 128 + aRow1) * K + ak + aC1, true);
        cp16(bd + (bRow0 * BSTR + bC0) * 2,
             bSrc + (size_t)(bk + bRow0) * N + cColBase + bC0, bOk0);
        cp16(bd + (bRow1 * BSTR + bC1) * 2,
             bSrc + (size_t)(bk + bRow1) * N + cColBase + bC1, bOk1);
    };

    float acc[4][4][4];
#pragma unroll
    for (int i = 0; i < 4; i++)
#pragma unroll
        for (int j = 0; j < 4; j++)
#pragma unroll
            for (int r = 0; r < 4; r++) acc[i][j][r] = 0.f;

    const int aLaneRow = wm * 64 + (lane & 15);
    const int aLaneK   = (lane >> 4) << 3;
    const int bLaneK   = lane & 15;
    const int bLaneCol = wn * 32;

#pragma unroll
    for (int s = 0; s < STG - 1; s++) { issue(s); cp_commit(); }
    cp_wait<STG - 2>();
    __syncthreads();

    for (int it = 0; it < nIter; it++) {
        const int cur = it % STG;
        if (it + STG - 1 < nIter) issue(it + STG - 1);
        cp_commit();

        const uint32_t aB = aBase + cur * ASZB;
        const uint32_t bB = bBase + cur * BSZB;
#pragma unroll
        for (int kk = 0; kk < 32; kk += 16) {
            uint32_t a[4][4], b[4][2];
#pragma unroll
            for (int mt = 0; mt < 4; mt++) {
                uint32_t off = ((aLaneRow + mt * 16) * ASTR + kk + aLaneK) * 2;
                ldsm_x4(aB + off, a[mt][0], a[mt][1], a[mt][2], a[mt][3]);
            }
#pragma unroll
            for (int nt = 0; nt < 4; nt++) {
                uint32_t off = ((kk + bLaneK) * BSTR + bLaneCol + nt * 8) * 2;
                ldsm_x2t(bB + off, b[nt][0], b[nt][1]);
            }
#pragma unroll
            for (int mt = 0; mt < 4; mt++)
#pragma unroll
                for (int nt = 0; nt < 4; nt++)
                    mma_bf16(acc[mt][nt], a[mt], b[nt]);
        }
        cp_wait<STG - 2>();
        __syncthreads();
    }

    const int rBase = by * 128 + wm * 64 + (lane >> 2);
    const int cBase = cColBase + wn * 32 + (lane & 3) * 2;
#pragma unroll
    for (int mt = 0; mt < 4; mt++)
#pragma unroll
        for (int nt = 0; nt < 4; nt++) {
            int r0 = rBase + mt * 16;
            int c0 = cBase + nt * 8;
            if (c0 < N) {
                *reinterpret_cast<float2*>(C + (size_t)r0 * N + c0) =
                    make_float2(acc[mt][nt][0], acc[mt][nt][1]);
                *reinterpret_cast<float2*>(C + (size_t)(r0 + 8) * N + c0) =
                    make_float2(acc[mt][nt][2], acc[mt][nt][3]);
            }
        }
}

// ---------------- RoPE ----------------
__global__ void rope_kernel(const float* __restrict__ cosp, const float* __restrict__ sinp) {
    int t = blockIdx.x;
    float* row = g_qkvw + (size_t)t * OUTD;
    for (int i = threadIdx.x; i < (H_ + HKV) * 32; i += blockDim.x) {
        int head = i >> 5, dp = i & 31;
        float* base = (head < H_) ? (row + OQ + head * DQK)
                                  : (row + OK_ + (head - H_) * DQK);
        float x1 = base[dp], x2 = base[dp + 32];
        float c1 = cosp[t * DQK + dp],      s1 = sinp[t * DQK + dp];
        float c2 = cosp[t * DQK + dp + 32], s2 = sinp[t * DQK + dp + 32];
        base[dp]      = x1 * c1 - x2 * s1;
        base[dp + 32] = x2 * c2 + x1 * s2;
    }
}

// ---------------- mean pool ----------------
__global__ void pool_kernel() {
    int idx = blockIdx.x * blockDim.x + threadIdx.x;
    if (idx >= NB * G_ * DQK) return;
    int nb = idx / (G_ * DQK);
    int g  = (idx / DQK) % G_;
    int d  = idx % DQK;
    float sk = 0.f, sv = 0.f;
    for (int i = 0; i < BLK; i++) {
        const float* r = g_qkvw + (size_t)(nb * BLK + i) * OUTD;
        sk += r[OK_ + g * DQK + d];
        sv += r[OV  + g * DV  + d];
    }
    g_kcmp[idx] = sk * (1.f / BLK);
    g_vcmp[idx] = sv * (1.f / BLK);
}

// ---------------- compressed branch + top-k ----------------
__global__ void cmp_kernel2() {
    extern __shared__ float sm[];
    float* kbuf = sm;
    float* p    = sm + 4096;
    float* imp  = p + TT * 16 * 64;
    const int t0 = blockIdx.x * TT;
    const int g  = blockIdx.y;
    const int tid = threadIdx.x;

    for (int i = tid; i < NB * DQK / 4; i += 256) {
        int n = i >> 4, d4 = (i & 15) << 2;
        *reinterpret_cast<float4*>(&kbuf[n * 64 + d4]) =
            *reinterpret_cast<const float4*>(&g_kcmp[(n * G_ + g) * DQK + d4]);
    }
    __syncthreads();

    const int row = tid >> 1;
    const int tt = row >> 4, hh = row & 15;
    const int t = t0 + tt;
    const int half = tid & 1;
    {
        float4 q[16];
        const float4* qp = reinterpret_cast<const float4*>(
            g_qkvw + (size_t)t * OUTD + OQ + (g * HG + hh) * DQK);
#pragma unroll
        for (int i = 0; i < 16; i++) q[i] = qp[i];
        const int nvis = (t + 1) >> 5;
        float* prow = p + row * 64;
        for (int n = half * 32; n < half * 32 + 32; n++) {
            float s = NEGI;
            if (n < nvis) {
                float a = 0.f;
#pragma unroll
                for (int i = 0; i < 16; i++) {
                    float4 kv = *reinterpret_cast<float4*>(&kbuf[n * 64 + i * 4]);
                    a += q[i].x * kv.x + q[i].y * kv.y + q[i].z * kv.z + q[i].w * kv.w;
                }
                s = a * SCALE;
            }
            prow[n] = s;
        }
    }
    __syncthreads();

    for (int i = tid; i < NB * DV / 4; i += 256) {
        int n = i >> 4, d4 = (i & 15) << 2;
        *reinterpret_cast<float4*>(&kbuf[n * 64 + d4]) =
            *reinterpret_cast<const float4*>(&g_vcmp[(n * G_ + g) * DV + d4]);
    }
    if (tid < 128) {
        float* pr = p + tid * 64;
        int tloc = t0 + (tid >> 4);
        int nv = (tloc + 1) >> 5;
        if (nv == 0) {
            for (int n = 0; n < 64; n++) pr[n] = 0.f;
        } else {
            float m = NEGI;
            for (int n = 0; n < 64; n++) m = fmaxf(m, pr[n]);
            float s = 0.f;
            for (int n = 0; n < 64; n++) { float e = __expf(pr[n] - m); pr[n] = e; s += e; }
            float inv = 1.f / s;
            for (int n = 0; n < 64; n++) pr[n] *= inv;
        }
    }
    __syncthreads();

    for (int i = tid; i < TT * NB; i += 256) {
        int tti = i >> 6, n = i & 63;
        int tloc = t0 + tti, cur = tloc >> 5;
        float v;
        if (n > cur) v = NEGI;
        else {
            v = 0.f;
            for (int h2 = 0; h2 < 16; h2++) v += p[(tti * 16 + h2) * 64 + n];
            if (n == 0)   v += 1e4f;
            if (n == cur) v += 1e4f;
        }
        imp[i] = v;
    }
    __syncthreads();

    {
        int wid = tid >> 5, lane = tid & 31;
        if (wid < TT) {
            float v0 = imp[wid * 64 + lane];
            float v1 = imp[wid * 64 + 32 + lane];
            int* outp = g_selidx + ((t0 + wid) * G_ + g) * NSEL;
            for (int j = 0; j < NSEL; j++) {
                float bv = v0; int bi = lane;
                if (v1 > bv) { bv = v1; bi = lane + 32; }
#pragma unroll
                for (int off = 16; off; off >>= 1) {
                    float ov = __shfl_xor_sync(0xffffffffu, bv, off);
                    int   oi = __shfl_xor_sync(0xffffffffu, bi, off);
                    if (ov > bv || (ov == bv && oi < bi)) { bv = ov; bi = oi; }
                }
                if (lane == 0) outp[j] = bi;
                if (bi == lane)      v0 = -2e30f;
                if (bi == lane + 32) v1 = -2e30f;
            }
        }
    }

    {
        const int nv = (t + 1) >> 5;
        float acc[32];
#pragma unroll
        for (int i = 0; i < 32; i++) acc[i] = 0.f;
        const float* pr = p + row * 64;
        for (int n = 0; n < nv; n++) {
            float w = pr[n];
            const float* vr = kbuf + n * 64 + half * 32;
#pragma unroll
            for (int i = 0; i < 8; i++) {
                float4 v4 = *reinterpret_cast<const float4*>(&vr[i * 4]);
                acc[i * 4 + 0] += w * v4.x; acc[i * 4 + 1] += w * v4.y;
                acc[i * 4 + 2] += w * v4.z; acc[i * 4 + 3] += w * v4.w;
            }
        }
        float* op = g_ocmp + ((size_t)t * H_ + g * HG + hh) * DV + half * 32;
#pragma unroll
        for (int i = 0; i < 8; i++)
            *reinterpret_cast<float4*>(&op[i * 4]) =
                make_float4(acc[i * 4], acc[i * 4 + 1], acc[i * 4 + 2], acc[i * 4 + 3]);
    }
}

// ---------------- selection branch (padded, half-buffered) ----------------
// grid (T, G), 256 threads. smem: kbuf[128*KSTR] + p[16*256] + qs[16*64]
__global__ void sel_kernel3() {
    extern __shared__ float sm[];
    float* kbuf = sm;                        // 128 rows, KSTR stride
    float* p    = sm + 128 * KSTR;
    float* qs   = p + 16 * 256;
    __shared__ int sidx[NSEL];
    const int t = blockIdx.x, g = blockIdx.y, tid = threadIdx.x;
    const int hh = tid >> 4, rb = tid & 15;

    if (tid < NSEL) sidx[tid] = g_selidx[(t * G_ + g) * NSEL + tid];
    for (int i = tid; i < HG * DQK / 4; i += 256) {
        int h2 = i >> 4, d4 = (i & 15) << 2;
        *reinterpret_cast<float4*>(&qs[h2 * 64 + d4]) =
            *reinterpret_cast<const float4*>(g_qkvw + (size_t)t * OUTD + OQ + (g * HG + h2) * DQK + d4);
    }
    __syncthreads();

    float4 q[16];
#pragma unroll
    for (int i = 0; i < 16; i++) q[i] = *reinterpret_cast<float4*>(&qs[hh * 64 + i * 4]);

    // ---- scores in 2 half-passes over K ----
#pragma unroll
    for (int hf = 0; hf < 2; hf++) {
        for (int i = tid; i < 128 * 16; i += 256) {          // 128 rows x 16 float4
            int r = i >> 4, d4 = (i & 15) << 2;
            int rg = hf * 128 + r;
            int rowg = sidx[rg >> 5] * BLK + (rg & 31);
            *reinterpret_cast<float4*>(&kbuf[r * KSTR + d4]) =
                *reinterpret_cast<const float4*>(g_qkvw + (size_t)rowg * OUTD + OK_ + g * DQK + d4);
        }
        __syncthreads();
#pragma unroll
        for (int k = 0; k < 8; k++) {
            int r = rb + k * 16;                              // 0..127
            int rg = hf * 128 + r;
            int pos = sidx[rg >> 5] * BLK + (rg & 31);
            float s = NEGI;
            if (pos <= t) {
                float a = 0.f;
#pragma unroll
                for (int i = 0; i < 16; i++) {
                    float4 kv = *reinterpret_cast<float4*>(&kbuf[r * KSTR + i * 4]);
                    a += q[i].x * kv.x + q[i].y * kv.y + q[i].z * kv.z + q[i].w * kv.w;
                }
                s = a * SCALE;
            }
            p[hh * 256 + rg] = s;
        }
        __syncthreads();
    }

    // ---- softmax over 256 (warp-parallel, 2 rows per warp) ----
    {
        int wid = tid >> 5, lane = tid & 31;
#pragma unroll
        for (int rr = 0; rr < 2; rr++) {
            float* pr = p + (wid * 2 + rr) * 256;
            float v[8];
            float m = NEGI;
#pragma unroll
            for (int i = 0; i < 8; i++) { v[i] = pr[i * 32 + lane]; m = fmaxf(m, v[i]); }
#pragma unroll
            for (int off = 16; off; off >>= 1) m = fmaxf(m, __shfl_xor_sync(0xffffffffu, m, off));
            float s = 0.f;
#pragma unroll
            for (int i = 0; i < 8; i++) { v[i] = __expf(v[i] - m); s += v[i]; }
#pragma unroll
            for (int off = 16; off; off >>= 1) s += __shfl_xor_sync(0xffffffffu, s, off);
            float inv = 1.f / s;
#pragma unroll
            for (int i = 0; i < 8; i++) pr[i * 32 + lane] = v[i] * inv;
        }
    }
    __syncthreads();

    // ---- o = p @ V in 2 half-passes ----
    const int d0 = (tid & 15) << 2;
    float4 acc = make_float4(0.f, 0.f, 0.f, 0.f);
    const float* pr = p + hh * 256;
#pragma unroll
    for (int hf = 0; hf < 2; hf++) {
        for (int i = tid; i < 128 * 16; i += 256) {
            int r = i >> 4, d4 = (i & 15) << 2;
            int rg = hf * 128 + r;
            int rowg = sidx[rg >> 5] * BLK + (rg & 31);
            *reinterpret_cast<float4*>(&kbuf[r * KSTR + d4]) =
                *reinterpret_cast<const float4*>(g_qkvw + (size_t)rowg * OUTD + OV + g * DV + d4);
        }
        __syncthreads();
#pragma unroll 4
        for (int r = 0; r < 128; r++) {
            float w = pr[hf * 128 + r];
            float4 v4 = *reinterpret_cast<float4*>(&kbuf[r * KSTR + d0]);
            acc.x += w * v4.x; acc.y += w * v4.y; acc.z += w * v4.z; acc.w += w * v4.w;
        }
        __syncthreads();
    }
    *reinterpret_cast<float4*>(g_osel + ((size_t)t * H_ + g * HG + hh) * DV + d0) = acc;
}

// ---------------- sliding-window branch (padded, half-buffered) ----------------
__global__ void win_kernel3() {
    extern __shared__ float sm[];
    float* kbuf = sm;
    float* p    = sm + 128 * KSTR;
    float* qs   = p + 16 * 256;
    const int t = blockIdx.x, g = blockIdx.y, tid = threadIdx.x;
    const int hh = tid >> 4, rb = tid & 15;
    const int w0 = t - (WINSZ - 1);

    for (int i = tid; i < HG * DQK / 4; i += 256) {
        int h2 = i >> 4, d4 = (i & 15) << 2;
        *reinterpret_cast<float4*>(&qs[h2 * 64 + d4]) =
            *reinterpret_cast<const float4*>(g_qkvw + (size_t)t * OUTD + OQ + (g * HG + h2) * DQK + d4);
    }
    __syncthreads();

    float4 q[16];
#pragma unroll
    for (int i = 0; i < 16; i++) q[i] = *reinterpret_cast<float4*>(&qs[hh * 64 + i * 4]);

#pragma unroll
    for (int hf = 0; hf < 2; hf++) {
        for (int i = tid; i < 128 * 16; i += 256) {
            int r = i >> 4, d4 = (i & 15) << 2;
            int pos = w0 + hf * 128 + r;
            int rc = pos < 0 ? 0 : pos;
            *reinterpret_cast<float4*>(&kbuf[r * KSTR + d4]) =
                *reinterpret_cast<const float4*>(g_qkvw + (size_t)rc * OUTD + OK_ + g * DQK + d4);
        }
        __syncthreads();
#pragma unroll
        for (int k = 0; k < 8; k++) {
            int r = rb + k * 16;
            int rg = hf * 128 + r;
            float s = NEGI;
            if (w0 + rg >= 0) {
                float a = 0.f;
#pragma unroll
                for (int i = 0; i < 16; i++) {
                    float4 kv = *reinterpret_cast<float4*>(&kbuf[r * KSTR + i * 4]);
                    a += q[i].x * kv.x + q[i].y * kv.y + q[i].z * kv.z + q[i].w * kv.w;
                }
                s = a * SCALE;
            }
            p[hh * 256 + rg] = s;
        }
        __syncthreads();
    }

    {
        int wid = tid >> 5, lane = tid & 31;
#pragma unroll
        for (int rr = 0; rr < 2; rr++) {
            float* pr = p + (wid * 2 + rr) * 256;
            float v[8];
            float m = NEGI;
#pragma unroll
            for (int i = 0; i < 8; i++) { v[i] = pr[i * 32 + lane]; m = fmaxf(m, v[i]); }
#pragma unroll
            for (int off = 16; off; off >>= 1) m = fmaxf(m, __shfl_xor_sync(0xffffffffu, m, off));
            float s = 0.f;
#pragma unroll
            for (int i = 0; i < 8; i++) { v[i] = __expf(v[i] - m); s += v[i]; }
#pragma unroll
            for (int off = 16; off; off >>= 1) s += __shfl_xor_sync(0xffffffffu, s, off);
            float inv = 1.f / s;
#pragma unroll
            for (int i = 0; i < 8; i++) pr[i * 32 + lane] = v[i] * inv;
        }
    }
    __syncthreads();

    const int d0 = (tid & 15) << 2;
    float4 acc = make_float4(0.f, 0.f, 0.f, 0.f);
    const float* pr = p + hh * 256;
#pragma unroll
    for (int hf = 0; hf < 2; hf++) {
        for (int i = tid; i < 128 * 16; i += 256) {
            int r = i >> 4, d4 = (i & 15) << 2;
            int pos = w0 + hf * 128 + r;
            int rc = pos < 0 ? 0 : pos;
            *reinterpret_cast<float4*>(&kbuf[r * KSTR + d4]) =
                *reinterpret_cast<const float4*>(g_qkvw + (size_t)rc * OUTD + OV + g * DV + d4);
        }
        __syncthreads();
#pragma unroll 4
        for (int r = 0; r < 128; r++) {
            float w = pr[hf * 128 + r];       // exactly 0 for masked rows
            float4 v4 = *reinterpret_cast<float4*>(&kbuf[r * KSTR + d0]);
            acc.x += w * v4.x; acc.y += w * v4.y; acc.z += w * v4.z; acc.w += w * v4.w;
        }
        __syncthreads();
    }
    *reinterpret_cast<float4*>(g_owin + ((size_t)t * H_ + g * HG + hh) * DV + d0) = acc;
}

// ---------------- gated combine + bf16 split ----------------
__global__ void combine_split_kernel() {
    int i = blockIdx.x * blockDim.x + threadIdx.x;
    if (i >= T_ * H_ * DV / 2) return;
    int e = 2 * i;
    int h = (e >> 6) & 31;
    int t = e >> 11;
    const float* wrow = g_qkvw + (size_t)t * OUTD + OW + h * 3;
    float g0 = 1.f / (1.f + __expf(-wrow[0]));
    float g1 = 1.f / (1.f + __expf(-wrow[1]));
    float g2 = 1.f / (1.f + __expf(-wrow[2]));
    float o0 = g0 * g_ocmp[e]     + g1 * g_osel[e]     + g2 * g_owin[e];
    float o1 = g0 * g_ocmp[e + 1] + g1 * g_osel[e + 1] + g2 * g_owin[e + 1];
    uint32_t hi, lo;
    split2(o0, o1, hi, lo);
    reinterpret_cast<uint32_t*>(g_och)[i] = hi;
    reinterpret_cast<uint32_t*>(g_ocl)[i] = lo;
}

// ---------------- launch ----------------
extern "C" void kernel_launch(void* const* d_in, const int* in_sizes, int n_in,
                              void* d_out, int out_size) {
    const float* x    = (const float*)d_in[0];
    const float* cosp = (const float*)d_in[1];
    const float* sinp = (const float*)d_in[2];
    const float* wqkv = (const float*)d_in[3];
    const float* ow   = (const float*)d_in[4];
    float* out = (float*)d_out;

    float* qkvw_p;
    cudaGetSymbolAddress((void**)&qkvw_p, g_qkvw);
    __nv_bfloat16 *xh, *xl, *wh, *wl, *owh, *owl, *och, *ocl;
    cudaGetSymbolAddress((void**)&xh, g_xh);   cudaGetSymbolAddress((void**)&xl, g_xl);
    cudaGetSymbolAddress((void**)&wh, g_wh);   cudaGetSymbolAddress((void**)&wl, g_wl);
    cudaGetSymbolAddress((void**)&owh, g_owh); cudaGetSymbolAddress((void**)&owl, g_owl);
    cudaGetSymbolAddress((void**)&och, g_och); cudaGetSymbolAddress((void**)&ocl, g_ocl);

    const int CMP_SMEM = (64 * 64 + TT * 16 * 64 + TT * 64) * 4;
    const int SW_SMEM  = (128 * KSTR + 16 * 256 + 16 * 64) * 4;   // 55296 B -> 4 CTAs/SM
    cudaFuncSetAttribute((const void*)gemm_k3, cudaFuncAttributeMaxDynamicSharedMemorySize, GEMM_SMEM);
    cudaFuncSetAttribute((const void*)cmp_kernel2, cudaFuncAttributeMaxDynamicSharedMemorySize, CMP_SMEM);
    cudaFuncSetAttribute((const void*)sel_kernel3, cudaFuncAttributeMaxDynamicSharedMemorySize, SW_SMEM);
    cudaFuncSetAttribute((const void*)win_kernel3, cudaFuncAttributeMaxDynamicSharedMemorySize, SW_SMEM);

    split_kernel<<<(T_ * HID / 2 + 255) / 256, 256>>>(x, xh, xl, T_ * HID / 2);
    split_kernel<<<(HID * OUTD / 2 + 255) / 256, 256>>>(wqkv, wh, wl, HID * OUTD / 2);
    split_kernel<<<(H_ * DV * HID / 2 + 255) / 256, 256>>>(ow, owh, owl, H_ * DV * HID / 2);

    dim3 g1((OUTD + 127) / 128, T_ / 128);
    gemm_k3<<<g1, 256, GEMM_SMEM>>>(xh, xl, wh, wl, qkvw_p, T_, OUTD, HID);

    rope_kernel<<<T_, 256>>>(cosp, sinp);
    pool_kernel<<<(NB * G_ * DQK + 255) / 256, 256>>>();

    dim3 gc(T_ / TT, G_);
    cmp_kernel2<<<gc, 256, CMP_SMEM>>>();

    dim3 gt(T_, G_);
    sel_kernel3<<<gt, 256, SW_SMEM>>>();
    win_kernel3<<<gt, 256, SW_SMEM>>>();

    combine_split_kernel<<<(T_ * H_ * DV / 2 + 255) / 256, 256>>>();

    dim3 g2(HID / 128, T_ / 128);
    gemm_k3<<<g2, 256, GEMM_SMEM>>>(och, ocl, owh, owl, out, T_, HID, HID);
}

// round 9
// speedup vs baseline: 3.5313x; 1.0047x over previous
#include <cuda_runtime.h>
#include <cuda_bf16.h>
#include <math.h>
#include <stdint.h>

// ---------------- problem constants ----------------
namespace {
constexpr int T_    = 2048;
constexpr int HID   = 2048;
constexpr int H_    = 32;
constexpr int HKV   = 2;
constexpr int DQK   = 64;
constexpr int DV    = 64;
constexpr int G_    = 2;
constexpr int HG    = 16;
constexpr int BLK   = 32;
constexpr int NSEL  = 8;
constexpr int WINSZ = 256;
constexpr int NB    = 64;
constexpr int OUTD  = 2400;
constexpr int OQ = 0;
constexpr int OK_ = 2048;
constexpr int OV  = 2176;
constexpr int OW  = 2304;
constexpr float SCALE = 0.125f;
constexpr float NEGI  = -1e30f;
constexpr int TT = 8;
constexpr int KSTR = 68;                 // padded smem row stride (floats) for sel/win

// GEMM tiling
constexpr int STG  = 4;                  // deeper cp.async pipeline
constexpr int ASTR = 40;
constexpr int BSTR = 136;
constexpr int ASZB = 128 * ASTR * 2;
constexpr int BSZB = 32 * BSTR * 2;
constexpr int GEMM_SMEM = STG * (ASZB + BSZB);   // 75776 B, 2 CTAs/SM fit
}

// ---------------- scratch ----------------
__device__ float g_qkvw[(size_t)T_ * OUTD];
__device__ float g_kcmp[NB * G_ * DQK];
__device__ float g_vcmp[NB * G_ * DV];
__device__ float g_ocmp[(size_t)T_ * H_ * DV];
__device__ float g_osel[(size_t)T_ * H_ * DV];
__device__ float g_owin[(size_t)T_ * H_ * DV];
__device__ int   g_selidx[T_ * G_ * NSEL];
__device__ __nv_bfloat16 g_xh[(size_t)T_ * HID];
__device__ __nv_bfloat16 g_xl[(size_t)T_ * HID];
__device__ __nv_bfloat16 g_wh[(size_t)HID * OUTD];
__device__ __nv_bfloat16 g_wl[(size_t)HID * OUTD];
__device__ __nv_bfloat16 g_owh[(size_t)H_ * DV * HID];
__device__ __nv_bfloat16 g_owl[(size_t)H_ * DV * HID];
__device__ __nv_bfloat16 g_och[(size_t)T_ * H_ * DV];
__device__ __nv_bfloat16 g_ocl[(size_t)T_ * H_ * DV];

// ---------------- helpers ----------------
__device__ __forceinline__ uint32_t smem_u32(const void* p) {
    return (uint32_t)__cvta_generic_to_shared(p);
}
__device__ __forceinline__ void ldsm_x4(uint32_t addr, uint32_t& r0, uint32_t& r1,
                                        uint32_t& r2, uint32_t& r3) {
    asm volatile("ldmatrix.sync.aligned.m8n8.x4.shared.b16 {%0,%1,%2,%3}, [%4];"
                 : "=r"(r0), "=r"(r1), "=r"(r2), "=r"(r3) : "r"(addr));
}
__device__ __forceinline__ void ldsm_x2t(uint32_t addr, uint32_t& r0, uint32_t& r1) {
    asm volatile("ldmatrix.sync.aligned.m8n8.x2.trans.shared.b16 {%0,%1}, [%2];"
                 : "=r"(r0), "=r"(r1) : "r"(addr));
}
__device__ __forceinline__ void mma_bf16(float* c, const uint32_t* a, const uint32_t* b) {
    asm volatile(
        "mma.sync.aligned.m16n8k16.row.col.f32.bf16.bf16.f32 "
        "{%0,%1,%2,%3}, {%4,%5,%6,%7}, {%8,%9}, {%0,%1,%2,%3};"
        : "+f"(c[0]), "+f"(c[1]), "+f"(c[2]), "+f"(c[3])
        : "r"(a[0]), "r"(a[1]), "r"(a[2]), "r"(a[3]), "r"(b[0]), "r"(b[1]));
}
__device__ __forceinline__ void cp16(uint32_t dst, const void* src, bool pred) {
    int sz = pred ? 16 : 0;
    asm volatile("cp.async.cg.shared.global [%0], [%1], 16, %2;"
                 :: "r"(dst), "l"(src), "r"(sz));
}
__device__ __forceinline__ void cp_commit() { asm volatile("cp.async.commit_group;"); }
template <int N> __device__ __forceinline__ void cp_wait() {
    asm volatile("cp.async.wait_group %0;" :: "n"(N));
}
__device__ __forceinline__ void split2(float x, float y, uint32_t& hi, uint32_t& lo) {
    __nv_bfloat16 xh = __float2bfloat16(x);
    __nv_bfloat16 yh = __float2bfloat16(y);
    __nv_bfloat16 xl = __float2bfloat16(x - __bfloat162float(xh));
    __nv_bfloat16 yl = __float2bfloat16(y - __bfloat162float(yh));
    __nv_bfloat162 h2 = __nv_bfloat162(xh, yh);
    __nv_bfloat162 l2 = __nv_bfloat162(xl, yl);
    hi = *reinterpret_cast<uint32_t*>(&h2);
    lo = *reinterpret_cast<uint32_t*>(&l2);
}

// ---------------- fp32 -> bf16 hi/lo split ----------------
__global__ void split_kernel(const float* __restrict__ src,
                             __nv_bfloat16* __restrict__ hi,
                             __nv_bfloat16* __restrict__ lo, int n2) {
    int i = blockIdx.x * blockDim.x + threadIdx.x;
    if (i >= n2) return;
    float2 v = *reinterpret_cast<const float2*>(src + 2 * (size_t)i);
    uint32_t h, l;
    split2(v.x, v.y, h, l);
    reinterpret_cast<uint32_t*>(hi)[i] = h;
    reinterpret_cast<uint32_t*>(lo)[i] = l;
}

// ---------------- K-tripled bf16 GEMM ----------------
// C = Ah@Bh + Al@Bh + Ah@Bl (fp32 accum). 128x128 tile, BK=32 over K'=3K,
// 256 threads, 4-stage cp.async pipeline, 2 CTAs/SM.
__global__ void __launch_bounds__(256, 2)
gemm_k3(const __nv_bfloat16* __restrict__ Ah, const __nv_bfloat16* __restrict__ Al,
        const __nv_bfloat16* __restrict__ Bh, const __nv_bfloat16* __restrict__ Bl,
        float* __restrict__ C, int M, int N, int K) {
    extern __shared__ char smraw[];
    const uint32_t aBase = smem_u32(smraw);
    const uint32_t bBase = aBase + STG * ASZB;

    const int tid  = threadIdx.x;
    const int lane = tid & 31;
    const int wid  = tid >> 5;
    const int wm   = wid & 1;
    const int wn   = wid >> 1;
    const int bx = blockIdx.x, by = blockIdx.y;
    const int cColBase = bx * 128;
    const int nIter = 3 * K / 32;

    const int aRow0 = (tid * 2) >> 2,        aC0 = ((tid * 2) & 3) * 8;
    const int aRow1 = (tid * 2 + 1) >> 2,    aC1 = ((tid * 2 + 1) & 3) * 8;
    const int bRow0 = (tid * 2) >> 4,        bC0 = ((tid * 2) & 15) * 8;
    const int bRow1 = (tid * 2 + 1) >> 4,    bC1 = ((tid * 2 + 1) & 15) * 8;
    const bool bOk0 = (cColBase + bC0) < N;
    const bool bOk1 = (cColBase + bC1) < N;

    auto issue = [&](int it) {
        const int kIdx = it * 32;
        const int seg  = (kIdx >= 2 * K) ? 2 : (kIdx >= K ? 1 : 0);
        const __nv_bfloat16* aSrc = (seg == 1) ? Al : Ah;
        const __nv_bfloat16* bSrc = (seg == 2) ? Bl : Bh;
        const int ak = kIdx - seg * K;       // kIdx mod K
        const int bk = ak;
        const int st = it % STG;
        uint32_t ad = aBase + st * ASZB;
        uint32_t bd = bBase + st * BSZB;
        cp16(ad + (aRow0 * ASTR + aC0) * 2,
             aSrc + (size_t)(by * 128 + aRow0) * K + ak + aC0, true);
        cp16(ad + (aRow1 * ASTR + aC1) * 2,
             aSrc + (size_t)(by * 128 + aRow1) * K + ak + aC1, true);
        cp16(bd + (bRow0 * BSTR + bC0) * 2,
             bSrc + (size_t)(bk + bRow0) * N + cColBase + bC0, bOk0);
        cp16(bd + (bRow1 * BSTR + bC1) * 2,
             bSrc + (size_t)(bk + bRow1) * N + cColBase + bC1, bOk1);
    };

    float acc[4][4][4];
#pragma unroll
    for (int i = 0; i < 4; i++)
#pragma unroll
        for (int j = 0; j < 4; j++)
#pragma unroll
            for (int r = 0; r < 4; r++) acc[i][j][r] = 0.f;

    const int aLaneRow = wm * 64 + (lane & 15);
    const int aLaneK   = (lane >> 4) << 3;
    const int bLaneK   = lane & 15;
    const int bLaneCol = wn * 32;

#pragma unroll
    for (int s = 0; s < STG - 1; s++) { issue(s); cp_commit(); }
    cp_wait<STG - 2>();
    __syncthreads();

    for (int it = 0; it < nIter; it++) {
        const int cur = it % STG;
        if (it + STG - 1 < nIter) issue(it + STG - 1);
        cp_commit();

        const uint32_t aB = aBase + cur * ASZB;
        const uint32_t bB = bBase + cur * BSZB;
#pragma unroll
        for (int kk = 0; kk < 32; kk += 16) {
            uint32_t a[4][4], b[4][2];
#pragma unroll
            for (int mt = 0; mt < 4; mt++) {
                uint32_t off = ((aLaneRow + mt * 16) * ASTR + kk + aLaneK) * 2;
                ldsm_x4(aB + off, a[mt][0], a[mt][1], a[mt][2], a[mt][3]);
            }
#pragma unroll
            for (int nt = 0; nt < 4; nt++) {
                uint32_t off = ((kk + bLaneK) * BSTR + bLaneCol + nt * 8) * 2;
                ldsm_x2t(bB + off, b[nt][0], b[nt][1]);
            }
#pragma unroll
            for (int mt = 0; mt < 4; mt++)
#pragma unroll
                for (int nt = 0; nt < 4; nt++)
                    mma_bf16(acc[mt][nt], a[mt], b[nt]);
        }
        cp_wait<STG - 2>();
        __syncthreads();
    }

    const int rBase = by * 128 + wm * 64 + (lane >> 2);
    const int cBase = cColBase + wn * 32 + (lane & 3) * 2;
#pragma unroll
    for (int mt = 0; mt < 4; mt++)
#pragma unroll
        for (int nt = 0; nt < 4; nt++) {
            int r0 = rBase + mt * 16;
            int c0 = cBase + nt * 8;
            if (c0 < N) {
                *reinterpret_cast<float2*>(C + (size_t)r0 * N + c0) =
                    make_float2(acc[mt][nt][0], acc[mt][nt][1]);
                *reinterpret_cast<float2*>(C + (size_t)(r0 + 8) * N + c0) =
                    make_float2(acc[mt][nt][2], acc[mt][nt][3]);
            }
        }
}

// ---------------- RoPE ----------------
__global__ void rope_kernel(const float* __restrict__ cosp, const float* __restrict__ sinp) {
    int t = blockIdx.x;
    float* row = g_qkvw + (size_t)t * OUTD;
    for (int i = threadIdx.x; i < (H_ + HKV) * 32; i += blockDim.x) {
        int head = i >> 5, dp = i & 31;
        float* base = (head < H_) ? (row + OQ + head * DQK)
                                  : (row + OK_ + (head - H_) * DQK);
        float x1 = base[dp], x2 = base[dp + 32];
        float c1 = cosp[t * DQK + dp],      s1 = sinp[t * DQK + dp];
        float c2 = cosp[t * DQK + dp + 32], s2 = sinp[t * DQK + dp + 32];
        base[dp]      = x1 * c1 - x2 * s1;
        base[dp + 32] = x2 * c2 + x1 * s2;
    }
}

// ---------------- mean pool ----------------
__global__ void pool_kernel() {
    int idx = blockIdx.x * blockDim.x + threadIdx.x;
    if (idx >= NB * G_ * DQK) return;
    int nb = idx / (G_ * DQK);
    int g  = (idx / DQK) % G_;
    int d  = idx % DQK;
    float sk = 0.f, sv = 0.f;
    for (int i = 0; i < BLK; i++) {
        const float* r = g_qkvw + (size_t)(nb * BLK + i) * OUTD;
        sk += r[OK_ + g * DQK + d];
        sv += r[OV  + g * DV  + d];
    }
    g_kcmp[idx] = sk * (1.f / BLK);
    g_vcmp[idx] = sv * (1.f / BLK);
}

// ---------------- compressed branch + top-k ----------------
__global__ void cmp_kernel2() {
    extern __shared__ float sm[];
    float* kbuf = sm;
    float* p    = sm + 4096;
    float* imp  = p + TT * 16 * 64;
    const int t0 = blockIdx.x * TT;
    const int g  = blockIdx.y;
    const int tid = threadIdx.x;

    for (int i = tid; i < NB * DQK / 4; i += 256) {
        int n = i >> 4, d4 = (i & 15) << 2;
        *reinterpret_cast<float4*>(&kbuf[n * 64 + d4]) =
            *reinterpret_cast<const float4*>(&g_kcmp[(n * G_ + g) * DQK + d4]);
    }
    __syncthreads();

    const int row = tid >> 1;
    const int tt = row >> 4, hh = row & 15;
    const int t = t0 + tt;
    const int half = tid & 1;
    {
        float4 q[16];
        const float4* qp = reinterpret_cast<const float4*>(
            g_qkvw + (size_t)t * OUTD + OQ + (g * HG + hh) * DQK);
#pragma unroll
        for (int i = 0; i < 16; i++) q[i] = qp[i];
        const int nvis = (t + 1) >> 5;
        float* prow = p + row * 64;
        for (int n = half * 32; n < half * 32 + 32; n++) {
            float s = NEGI;
            if (n < nvis) {
                float a = 0.f;
#pragma unroll
                for (int i = 0; i < 16; i++) {
                    float4 kv = *reinterpret_cast<float4*>(&kbuf[n * 64 + i * 4]);
                    a += q[i].x * kv.x + q[i].y * kv.y + q[i].z * kv.z + q[i].w * kv.w;
                }
                s = a * SCALE;
            }
            prow[n] = s;
        }
    }
    __syncthreads();

    for (int i = tid; i < NB * DV / 4; i += 256) {
        int n = i >> 4, d4 = (i & 15) << 2;
        *reinterpret_cast<float4*>(&kbuf[n * 64 + d4]) =
            *reinterpret_cast<const float4*>(&g_vcmp[(n * G_ + g) * DV + d4]);
    }
    if (tid < 128) {
        float* pr = p + tid * 64;
        int tloc = t0 + (tid >> 4);
        int nv = (tloc + 1) >> 5;
        if (nv == 0) {
            for (int n = 0; n < 64; n++) pr[n] = 0.f;
        } else {
            float m = NEGI;
            for (int n = 0; n < 64; n++) m = fmaxf(m, pr[n]);
            float s = 0.f;
            for (int n = 0; n < 64; n++) { float e = __expf(pr[n] - m); pr[n] = e; s += e; }
            float inv = 1.f / s;
            for (int n = 0; n < 64; n++) pr[n] *= inv;
        }
    }
    __syncthreads();

    for (int i = tid; i < TT * NB; i += 256) {
        int tti = i >> 6, n = i & 63;
        int tloc = t0 + tti, cur = tloc >> 5;
        float v;
        if (n > cur) v = NEGI;
        else {
            v = 0.f;
            for (int h2 = 0; h2 < 16; h2++) v += p[(tti * 16 + h2) * 64 + n];
            if (n == 0)   v += 1e4f;
            if (n == cur) v += 1e4f;
        }
        imp[i] = v;
    }
    __syncthreads();

    {
        int wid = tid >> 5, lane = tid & 31;
        if (wid < TT) {
            float v0 = imp[wid * 64 + lane];
            float v1 = imp[wid * 64 + 32 + lane];
            int* outp = g_selidx + ((t0 + wid) * G_ + g) * NSEL;
            for (int j = 0; j < NSEL; j++) {
                float bv = v0; int bi = lane;
                if (v1 > bv) { bv = v1; bi = lane + 32; }
#pragma unroll
                for (int off = 16; off; off >>= 1) {
                    float ov = __shfl_xor_sync(0xffffffffu, bv, off);
                    int   oi = __shfl_xor_sync(0xffffffffu, bi, off);
                    if (ov > bv || (ov == bv && oi < bi)) { bv = ov; bi = oi; }
                }
                if (lane == 0) outp[j] = bi;
                if (bi == lane)      v0 = -2e30f;
                if (bi == lane + 32) v1 = -2e30f;
            }
        }
    }

    {
        const int nv = (t + 1) >> 5;
        float acc[32];
#pragma unroll
        for (int i = 0; i < 32; i++) acc[i] = 0.f;
        const float* pr = p + row * 64;
        for (int n = 0; n < nv; n++) {
            float w = pr[n];
            const float* vr = kbuf + n * 64 + half * 32;
#pragma unroll
            for (int i = 0; i < 8; i++) {
                float4 v4 = *reinterpret_cast<const float4*>(&vr[i * 4]);
                acc[i * 4 + 0] += w * v4.x; acc[i * 4 + 1] += w * v4.y;
                acc[i * 4 + 2] += w * v4.z; acc[i * 4 + 3] += w * v4.w;
            }
        }
        float* op = g_ocmp + ((size_t)t * H_ + g * HG + hh) * DV + half * 32;
#pragma unroll
        for (int i = 0; i < 8; i++)
            *reinterpret_cast<float4*>(&op[i * 4]) =
                make_float4(acc[i * 4], acc[i * 4 + 1], acc[i * 4 + 2], acc[i * 4 + 3]);
    }
}

// ---------------- selection branch ----------------
__global__ void sel_kernel3() {
    extern __shared__ float sm[];
    float* kbuf = sm;
    float* p    = sm + 128 * KSTR;
    float* qs   = p + 16 * 256;
    __shared__ int sidx[NSEL];
    const int t = blockIdx.x, g = blockIdx.y, tid = threadIdx.x;
    const int hh = tid >> 4, rb = tid & 15;

    if (tid < NSEL) sidx[tid] = g_selidx[(t * G_ + g) * NSEL + tid];
    for (int i = tid; i < HG * DQK / 4; i += 256) {
        int h2 = i >> 4, d4 = (i & 15) << 2;
        *reinterpret_cast<float4*>(&qs[h2 * 64 + d4]) =
            *reinterpret_cast<const float4*>(g_qkvw + (size_t)t * OUTD + OQ + (g * HG + h2) * DQK + d4);
    }
    __syncthreads();

    float4 q[16];
#pragma unroll
    for (int i = 0; i < 16; i++) q[i] = *reinterpret_cast<float4*>(&qs[hh * 64 + i * 4]);

#pragma unroll
    for (int hf = 0; hf < 2; hf++) {
        for (int i = tid; i < 128 * 16; i += 256) {
            int r = i >> 4, d4 = (i & 15) << 2;
            int rg = hf * 128 + r;
            int rowg = sidx[rg >> 5] * BLK + (rg & 31);
            *reinterpret_cast<float4*>(&kbuf[r * KSTR + d4]) =
                *reinterpret_cast<const float4*>(g_qkvw + (size_t)rowg * OUTD + OK_ + g * DQK + d4);
        }
        __syncthreads();
#pragma unroll
        for (int k = 0; k < 8; k++) {
            int r = rb + k * 16;
            int rg = hf * 128 + r;
            int pos = sidx[rg >> 5] * BLK + (rg & 31);
            float s = NEGI;
            if (pos <= t) {
                float a = 0.f;
#pragma unroll
                for (int i = 0; i < 16; i++) {
                    float4 kv = *reinterpret_cast<float4*>(&kbuf[r * KSTR + i * 4]);
                    a += q[i].x * kv.x + q[i].y * kv.y + q[i].z * kv.z + q[i].w * kv.w;
                }
                s = a * SCALE;
            }
            p[hh * 256 + rg] = s;
        }
        __syncthreads();
    }

    {
        int wid = tid >> 5, lane = tid & 31;
#pragma unroll
        for (int rr = 0; rr < 2; rr++) {
            float* pr = p + (wid * 2 + rr) * 256;
            float v[8];
            float m = NEGI;
#pragma unroll
            for (int i = 0; i < 8; i++) { v[i] = pr[i * 32 + lane]; m = fmaxf(m, v[i]); }
#pragma unroll
            for (int off = 16; off; off >>= 1) m = fmaxf(m, __shfl_xor_sync(0xffffffffu, m, off));
            float s = 0.f;
#pragma unroll
            for (int i = 0; i < 8; i++) { v[i] = __expf(v[i] - m); s += v[i]; }
#pragma unroll
            for (int off = 16; off; off >>= 1) s += __shfl_xor_sync(0xffffffffu, s, off);
            float inv = 1.f / s;
#pragma unroll
            for (int i = 0; i < 8; i++) pr[i * 32 + lane] = v[i] * inv;
        }
    }
    __syncthreads();

    const int d0 = (tid & 15) << 2;
    float4 acc0 = make_float4(0.f, 0.f, 0.f, 0.f);
    float4 acc1 = make_float4(0.f, 0.f, 0.f, 0.f);
    const float* pr = p + hh * 256;
#pragma unroll
    for (int hf = 0; hf < 2; hf++) {
        for (int i = tid; i < 128 * 16; i += 256) {
            int r = i >> 4, d4 = (i & 15) << 2;
            int rg = hf * 128 + r;
            int rowg = sidx[rg >> 5] * BLK + (rg & 31);
            *reinterpret_cast<float4*>(&kbuf[r * KSTR + d4]) =
                *reinterpret_cast<const float4*>(g_qkvw + (size_t)rowg * OUTD + OV + g * DV + d4);
        }
        __syncthreads();
#pragma unroll 4
        for (int r = 0; r < 128; r += 2) {     // split dependency chain
            float w0 = pr[hf * 128 + r];
            float w1 = pr[hf * 128 + r + 1];
            float4 v0 = *reinterpret_cast<float4*>(&kbuf[r * KSTR + d0]);
            float4 v1 = *reinterpret_cast<float4*>(&kbuf[(r + 1) * KSTR + d0]);
            acc0.x += w0 * v0.x; acc0.y += w0 * v0.y; acc0.z += w0 * v0.z; acc0.w += w0 * v0.w;
            acc1.x += w1 * v1.x; acc1.y += w1 * v1.y; acc1.z += w1 * v1.z; acc1.w += w1 * v1.w;
        }
        __syncthreads();
    }
    float4 acc = make_float4(acc0.x + acc1.x, acc0.y + acc1.y,
                             acc0.z + acc1.z, acc0.w + acc1.w);
    *reinterpret_cast<float4*>(g_osel + ((size_t)t * H_ + g * HG + hh) * DV + d0) = acc;
}

// ---------------- sliding-window branch ----------------
__global__ void win_kernel3() {
    extern __shared__ float sm[];
    float* kbuf = sm;
    float* p    = sm + 128 * KSTR;
    float* qs   = p + 16 * 256;
    const int t = blockIdx.x, g = blockIdx.y, tid = threadIdx.x;
    const int hh = tid >> 4, rb = tid & 15;
    const int w0 = t - (WINSZ - 1);

    for (int i = tid; i < HG * DQK / 4; i += 256) {
        int h2 = i >> 4, d4 = (i & 15) << 2;
        *reinterpret_cast<float4*>(&qs[h2 * 64 + d4]) =
            *reinterpret_cast<const float4*>(g_qkvw + (size_t)t * OUTD + OQ + (g * HG + h2) * DQK + d4);
    }
    __syncthreads();

    float4 q[16];
#pragma unroll
    for (int i = 0; i < 16; i++) q[i] = *reinterpret_cast<float4*>(&qs[hh * 64 + i * 4]);

#pragma unroll
    for (int hf = 0; hf < 2; hf++) {
        for (int i = tid; i < 128 * 16; i += 256) {
            int r = i >> 4, d4 = (i & 15) << 2;
            int pos = w0 + hf * 128 + r;
            int rc = pos < 0 ? 0 : pos;
            *reinterpret_cast<float4*>(&kbuf[r * KSTR + d4]) =
                *reinterpret_cast<const float4*>(g_qkvw + (size_t)rc * OUTD + OK_ + g * DQK + d4);
        }
        __syncthreads();
#pragma unroll
        for (int k = 0; k < 8; k++) {
            int r = rb + k * 16;
            int rg = hf * 128 + r;
            float s = NEGI;
            if (w0 + rg >= 0) {
                float a = 0.f;
#pragma unroll
                for (int i = 0; i < 16; i++) {
                    float4 kv = *reinterpret_cast<float4*>(&kbuf[r * KSTR + i * 4]);
                    a += q[i].x * kv.x + q[i].y * kv.y + q[i].z * kv.z + q[i].w * kv.w;
                }
                s = a * SCALE;
            }
            p[hh * 256 + rg] = s;
        }
        __syncthreads();
    }

    {
        int wid = tid >> 5, lane = tid & 31;
#pragma unroll
        for (int rr = 0; rr < 2; rr++) {
            float* pr = p + (wid * 2 + rr) * 256;
            float v[8];
            float m = NEGI;
#pragma unroll
            for (int i = 0; i < 8; i++) { v[i] = pr[i * 32 + lane]; m = fmaxf(m, v[i]); }
#pragma unroll
            for (int off = 16; off; off >>= 1) m = fmaxf(m, __shfl_xor_sync(0xffffffffu, m, off));
            float s = 0.f;
#pragma unroll
            for (int i = 0; i < 8; i++) { v[i] = __expf(v[i] - m); s += v[i]; }
#pragma unroll
            for (int off = 16; off; off >>= 1) s += __shfl_xor_sync(0xffffffffu, s, off);
            float inv = 1.f / s;
#pragma unroll
            for (int i = 0; i < 8; i++) pr[i * 32 + lane] = v[i] * inv;
        }
    }
    __syncthreads();

    const int d0 = (tid & 15) << 2;
    float4 acc0 = make_float4(0.f, 0.f, 0.f, 0.f);
    float4 acc1 = make_float4(0.f, 0.f, 0.f, 0.f);
    const float* pr = p + hh * 256;
#pragma unroll
    for (int hf = 0; hf < 2; hf++) {
        for (int i = tid; i < 128 * 16; i += 256) {
            int r = i >> 4, d4 = (i & 15) << 2;
            int pos = w0 + hf * 128 + r;
            int rc = pos < 0 ? 0 : pos;
            *reinterpret_cast<float4*>(&kbuf[r * KSTR + d4]) =
                *reinterpret_cast<const float4*>(g_qkvw + (size_t)rc * OUTD + OV + g * DV + d4);
        }
        __syncthreads();
#pragma unroll 4
        for (int r = 0; r < 128; r += 2) {
            float w0v = pr[hf * 128 + r];
            float w1v = pr[hf * 128 + r + 1];
            float4 v0 = *reinterpret_cast<float4*>(&kbuf[r * KSTR + d0]);
            float4 v1 = *reinterpret_cast<float4*>(&kbuf[(r + 1) * KSTR + d0]);
            acc0.x += w0v * v0.x; acc0.y += w0v * v0.y; acc0.z += w0v * v0.z; acc0.w += w0v * v0.w;
            acc1.x += w1v * v1.x; acc1.y += w1v * v1.y; acc1.z += w1v * v1.z; acc1.w += w1v * v1.w;
        }
        __syncthreads();
    }
    float4 acc = make_float4(acc0.x + acc1.x, acc0.y + acc1.y,
                             acc0.z + acc1.z, acc0.w + acc1.w);
    *reinterpret_cast<float4*>(g_owin + ((size_t)t * H_ + g * HG + hh) * DV + d0) = acc;
}

// ---------------- gated combine + bf16 split ----------------
__global__ void combine_split_kernel() {
    int i = blockIdx.x * blockDim.x + threadIdx.x;
    if (i >= T_ * H_ * DV / 2) return;
    int e = 2 * i;
    int h = (e >> 6) & 31;
    int t = e >> 11;
    const float* wrow = g_qkvw + (size_t)t * OUTD + OW + h * 3;
    float g0 = 1.f / (1.f + __expf(-wrow[0]));
    float g1 = 1.f / (1.f + __expf(-wrow[1]));
    float g2 = 1.f / (1.f + __expf(-wrow[2]));
    float o0 = g0 * g_ocmp[e]     + g1 * g_osel[e]     + g2 * g_owin[e];
    float o1 = g0 * g_ocmp[e + 1] + g1 * g_osel[e + 1] + g2 * g_owin[e + 1];
    uint32_t hi, lo;
    split2(o0, o1, hi, lo);
    reinterpret_cast<uint32_t*>(g_och)[i] = hi;
    reinterpret_cast<uint32_t*>(g_ocl)[i] = lo;
}

// ---------------- launch ----------------
extern "C" void kernel_launch(void* const* d_in, const int* in_sizes, int n_in,
                              void* d_out, int out_size) {
    const float* x    = (const float*)d_in[0];
    const float* cosp = (const float*)d_in[1];
    const float* sinp = (const float*)d_in[2];
    const float* wqkv = (const float*)d_in[3];
    const float* ow   = (const float*)d_in[4];
    float* out = (float*)d_out;

    float* qkvw_p;
    cudaGetSymbolAddress((void**)&qkvw_p, g_qkvw);
    __nv_bfloat16 *xh, *xl, *wh, *wl, *owh, *owl, *och, *ocl;
    cudaGetSymbolAddress((void**)&xh, g_xh);   cudaGetSymbolAddress((void**)&xl, g_xl);
    cudaGetSymbolAddress((void**)&wh, g_wh);   cudaGetSymbolAddress((void**)&wl, g_wl);
    cudaGetSymbolAddress((void**)&owh, g_owh); cudaGetSymbolAddress((void**)&owl, g_owl);
    cudaGetSymbolAddress((void**)&och, g_och); cudaGetSymbolAddress((void**)&ocl, g_ocl);

    const int CMP_SMEM = (64 * 64 + TT * 16 * 64 + TT * 64) * 4;
    const int SW_SMEM  = (128 * KSTR + 16 * 256 + 16 * 64) * 4;
    cudaFuncSetAttribute((const void*)gemm_k3, cudaFuncAttributeMaxDynamicSharedMemorySize, GEMM_SMEM);
    cudaFuncSetAttribute((const void*)cmp_kernel2, cudaFuncAttributeMaxDynamicSharedMemorySize, CMP_SMEM);
    cudaFuncSetAttribute((const void*)sel_kernel3, cudaFuncAttributeMaxDynamicSharedMemorySize, SW_SMEM);
    cudaFuncSetAttribute((const void*)win_kernel3, cudaFuncAttributeMaxDynamicSharedMemorySize, SW_SMEM);

    split_kernel<<<(T_ * HID / 2 + 255) / 256, 256>>>(x, xh, xl, T_ * HID / 2);
    split_kernel<<<(HID * OUTD / 2 + 255) / 256, 256>>>(wqkv, wh, wl, HID * OUTD / 2);
    split_kernel<<<(H_ * DV * HID / 2 + 255) / 256, 256>>>(ow, owh, owl, H_ * DV * HID / 2);

    dim3 g1((OUTD + 127) / 128, T_ / 128);
    gemm_k3<<<g1, 256, GEMM_SMEM>>>(xh, xl, wh, wl, qkvw_p, T_, OUTD, HID);

    rope_kernel<<<T_, 256>>>(cosp, sinp);
    pool_kernel<<<(NB * G_ * DQK + 255) / 256, 256>>>();

    dim3 gc(T_ / TT, G_);
    cmp_kernel2<<<gc, 256, CMP_SMEM>>>();

    dim3 gt(T_, G_);
    sel_kernel3<<<gt, 256, SW_SMEM>>>();
    win_kernel3<<<gt, 256, SW_SMEM>>>();

    combine_split_kernel<<<(T_ * H_ * DV / 2 + 255) / 256, 256>>>();

    dim3 g2(HID / 128, T_ / 128);
    gemm_k3<<<g2, 256, GEMM_SMEM>>>(och, ocl, owh, owl, out, T_, HID, HID);
}

// round 10
// speedup vs baseline: 4.3846x; 1.2416x over previous
#include <cuda_runtime.h>
#include <cuda_bf16.h>
#include <math.h>
#include <stdint.h>

// ---------------- problem constants ----------------
namespace {
constexpr int T_    = 2048;
constexpr int HID   = 2048;
constexpr int H_    = 32;
constexpr int HKV   = 2;
constexpr int DQK   = 64;
constexpr int DV    = 64;
constexpr int G_    = 2;
constexpr int HG    = 16;
constexpr int BLK   = 32;
constexpr int NSEL  = 8;
constexpr int WINSZ = 256;
constexpr int NB    = 64;
constexpr int OUTD  = 2400;
constexpr int OQ = 0;
constexpr int OK_ = 2048;
constexpr int OV  = 2176;
constexpr int OW  = 2304;
constexpr float SCALE = 0.125f;
constexpr float NEGI  = -1e30f;
constexpr int TT = 8;

// GEMM tiling (unchanged, validated)
constexpr int STG  = 4;
constexpr int ASTR = 40;
constexpr int BSTR = 136;
constexpr int ASZB = 128 * ASTR * 2;
constexpr int BSZB = 32 * BSTR * 2;
constexpr int GEMM_SMEM = STG * (ASZB + BSZB);

// attn mma kernel smem layout (bytes)
constexpr int KT_LO_OFF = 33792;        // 64*264*2
constexpr int V_LO_OFF  = 36864;        // 256*72*2
constexpr int P_OFF     = 73728;        // KV region size (max of KT/V usage)
constexpr int PSM_LO    = 8448;         // 16*264*2
constexpr int Q_OFF     = P_OFF + 16896;        // 90624
constexpr int QL_OFF    = 2304;         // 16*72*2
constexpr int SIDX_OFF  = Q_OFF + 4608; // 95232
constexpr int ATT_SMEM  = SIDX_OFF + 32;        // 95264
constexpr int TPAD = T_ + 16;           // padded row length for K^T arrays
}

// ---------------- scratch ----------------
__device__ float g_qkvw[(size_t)T_ * OUTD];
__device__ float g_kcmp[NB * G_ * DQK];
__device__ float g_vcmp[NB * G_ * DV];
__device__ float g_ocmp[(size_t)T_ * H_ * DV];
__device__ float g_osel[(size_t)T_ * H_ * DV];
__device__ float g_owin[(size_t)T_ * H_ * DV];
__device__ int   g_selidx[T_ * G_ * NSEL];
__device__ __nv_bfloat16 g_xh[(size_t)T_ * HID];
__device__ __nv_bfloat16 g_xl[(size_t)T_ * HID];
__device__ __nv_bfloat16 g_wh[(size_t)HID * OUTD];
__device__ __nv_bfloat16 g_wl[(size_t)HID * OUTD];
__device__ __nv_bfloat16 g_owh[(size_t)H_ * DV * HID];
__device__ __nv_bfloat16 g_owl[(size_t)H_ * DV * HID];
__device__ __nv_bfloat16 g_och[(size_t)T_ * H_ * DV];
__device__ __nv_bfloat16 g_ocl[(size_t)T_ * H_ * DV];
// attention bf16 operands
__device__ __nv_bfloat16 g_qh[(size_t)T_ * H_ * DQK];
__device__ __nv_bfloat16 g_ql[(size_t)T_ * H_ * DQK];
__device__ __nv_bfloat16 g_khT[(size_t)G_ * DQK * TPAD];
__device__ __nv_bfloat16 g_klT[(size_t)G_ * DQK * TPAD];
__device__ __nv_bfloat16 g_vh[(size_t)T_ * G_ * DV];
__device__ __nv_bfloat16 g_vl[(size_t)T_ * G_ * DV];

// ---------------- helpers ----------------
__device__ __forceinline__ uint32_t smem_u32(const void* p) {
    return (uint32_t)__cvta_generic_to_shared(p);
}
__device__ __forceinline__ void ldsm_x4(uint32_t addr, uint32_t& r0, uint32_t& r1,
                                        uint32_t& r2, uint32_t& r3) {
    asm volatile("ldmatrix.sync.aligned.m8n8.x4.shared.b16 {%0,%1,%2,%3}, [%4];"
                 : "=r"(r0), "=r"(r1), "=r"(r2), "=r"(r3) : "r"(addr));
}
__device__ __forceinline__ void ldsm_x2t(uint32_t addr, uint32_t& r0, uint32_t& r1) {
    asm volatile("ldmatrix.sync.aligned.m8n8.x2.trans.shared.b16 {%0,%1}, [%2];"
                 : "=r"(r0), "=r"(r1) : "r"(addr));
}
__device__ __forceinline__ void mma_bf16(float* c, const uint32_t* a, const uint32_t* b) {
    asm volatile(
        "mma.sync.aligned.m16n8k16.row.col.f32.bf16.bf16.f32 "
        "{%0,%1,%2,%3}, {%4,%5,%6,%7}, {%8,%9}, {%0,%1,%2,%3};"
        : "+f"(c[0]), "+f"(c[1]), "+f"(c[2]), "+f"(c[3])
        : "r"(a[0]), "r"(a[1]), "r"(a[2]), "r"(a[3]), "r"(b[0]), "r"(b[1]));
}
__device__ __forceinline__ void cp16(uint32_t dst, const void* src, bool pred) {
    int sz = pred ? 16 : 0;
    asm volatile("cp.async.cg.shared.global [%0], [%1], 16, %2;"
                 :: "r"(dst), "l"(src), "r"(sz));
}
__device__ __forceinline__ void cp_commit() { asm volatile("cp.async.commit_group;"); }
template <int N> __device__ __forceinline__ void cp_wait() {
    asm volatile("cp.async.wait_group %0;" :: "n"(N));
}
__device__ __forceinline__ void split2(float x, float y, uint32_t& hi, uint32_t& lo) {
    __nv_bfloat16 xh = __float2bfloat16(x);
    __nv_bfloat16 yh = __float2bfloat16(y);
    __nv_bfloat16 xl = __float2bfloat16(x - __bfloat162float(xh));
    __nv_bfloat16 yl = __float2bfloat16(y - __bfloat162float(yh));
    __nv_bfloat162 h2 = __nv_bfloat162(xh, yh);
    __nv_bfloat162 l2 = __nv_bfloat162(xl, yl);
    hi = *reinterpret_cast<uint32_t*>(&h2);
    lo = *reinterpret_cast<uint32_t*>(&l2);
}

// ---------------- fp32 -> bf16 hi/lo split ----------------
__global__ void split_kernel(const float* __restrict__ src,
                             __nv_bfloat16* __restrict__ hi,
                             __nv_bfloat16* __restrict__ lo, int n2) {
    int i = blockIdx.x * blockDim.x + threadIdx.x;
    if (i >= n2) return;
    float2 v = *reinterpret_cast<const float2*>(src + 2 * (size_t)i);
    uint32_t h, l;
    split2(v.x, v.y, h, l);
    reinterpret_cast<uint32_t*>(hi)[i] = h;
    reinterpret_cast<uint32_t*>(lo)[i] = l;
}

// ---------------- split roped q/k/v into bf16 attention operands ----------------
// grid T_, 256 threads.  q -> [T,32,64] hi/lo, K -> [G,64,TPAD] hi/lo (transposed),
// V -> [T,G,64] hi/lo.
__global__ void split_qkv_kernel() {
    const int t = blockIdx.x, tid = threadIdx.x;
    const float* row = g_qkvw + (size_t)t * OUTD;
#pragma unroll
    for (int j = 0; j < 4; j++) {
        int ip = tid + 256 * j;                 // pair index over 32*64/2
        float2 v = *reinterpret_cast<const float2*>(row + OQ + 2 * ip);
        uint32_t h, l;
        split2(v.x, v.y, h, l);
        reinterpret_cast<uint32_t*>(g_qh)[(size_t)t * 1024 + ip] = h;
        reinterpret_cast<uint32_t*>(g_ql)[(size_t)t * 1024 + ip] = l;
    }
    if (tid < 128) {
        float v = row[OK_ + tid];
        int g = tid >> 6, d = tid & 63;
        __nv_bfloat16 h = __float2bfloat16(v);
        __nv_bfloat16 l = __float2bfloat16(v - __bfloat162float(h));
        g_khT[(size_t)(g * 64 + d) * TPAD + t] = h;
        g_klT[(size_t)(g * 64 + d) * TPAD + t] = l;
    } else {
        int e = tid - 128;
        float v = row[OV + e];
        int g = e >> 6, d = e & 63;
        __nv_bfloat16 h = __float2bfloat16(v);
        __nv_bfloat16 l = __float2bfloat16(v - __bfloat162float(h));
        g_vh[((size_t)t * G_ + g) * 64 + d] = h;
        g_vl[((size_t)t * G_ + g) * 64 + d] = l;
    }
}

// ---------------- K-tripled bf16 GEMM (unchanged, validated) ----------------
__global__ void __launch_bounds__(256, 2)
gemm_k3(const __nv_bfloat16* __restrict__ Ah, const __nv_bfloat16* __restrict__ Al,
        const __nv_bfloat16* __restrict__ Bh, const __nv_bfloat16* __restrict__ Bl,
        float* __restrict__ C, int M, int N, int K) {
    extern __shared__ char smraw[];
    const uint32_t aBase = smem_u32(smraw);
    const uint32_t bBase = aBase + STG * ASZB;

    const int tid  = threadIdx.x;
    const int lane = tid & 31;
    const int wid  = tid >> 5;
    const int wm   = wid & 1;
    const int wn   = wid >> 1;
    const int bx = blockIdx.x, by = blockIdx.y;
    const int cColBase = bx * 128;
    const int nIter = 3 * K / 32;

    const int aRow0 = (tid * 2) >> 2,        aC0 = ((tid * 2) & 3) * 8;
    const int aRow1 = (tid * 2 + 1) >> 2,    aC1 = ((tid * 2 + 1) & 3) * 8;
    const int bRow0 = (tid * 2) >> 4,        bC0 = ((tid * 2) & 15) * 8;
    const int bRow1 = (tid * 2 + 1) >> 4,    bC1 = ((tid * 2 + 1) & 15) * 8;
    const bool bOk0 = (cColBase + bC0) < N;
    const bool bOk1 = (cColBase + bC1) < N;

    auto issue = [&](int it) {
        const int kIdx = it * 32;
        const int seg  = (kIdx >= 2 * K) ? 2 : (kIdx >= K ? 1 : 0);
        const __nv_bfloat16* aSrc = (seg == 1) ? Al : Ah;
        const __nv_bfloat16* bSrc = (seg == 2) ? Bl : Bh;
        const int ak = kIdx - seg * K;
        const int bk = ak;
        const int st = it % STG;
        uint32_t ad = aBase + st * ASZB;
        uint32_t bd = bBase + st * BSZB;
        cp16(ad + (aRow0 * ASTR + aC0) * 2,
             aSrc + (size_t)(by * 128 + aRow0) * K + ak + aC0, true);
        cp16(ad + (aRow1 * ASTR + aC1) * 2,
             aSrc + (size_t)(by * 128 + aRow1) * K + ak + aC1, true);
        cp16(bd + (bRow0 * BSTR + bC0) * 2,
             bSrc + (size_t)(bk + bRow0) * N + cColBase + bC0, bOk0);
        cp16(bd + (bRow1 * BSTR + bC1) * 2,
             bSrc + (size_t)(bk + bRow1) * N + cColBase + bC1, bOk1);
    };

    float acc[4][4][4];
#pragma unroll
    for (int i = 0; i < 4; i++)
#pragma unroll
        for (int j = 0; j < 4; j++)
#pragma unroll
            for (int r = 0; r < 4; r++) acc[i][j][r] = 0.f;

    const int aLaneRow = wm * 64 + (lane & 15);
    const int aLaneK   = (lane >> 4) << 3;
    const int bLaneK   = lane & 15;
    const int bLaneCol = wn * 32;

#pragma unroll
    for (int s = 0; s < STG - 1; s++) { issue(s); cp_commit(); }
    cp_wait<STG - 2>();
    __syncthreads();

    for (int it = 0; it < nIter; it++) {
        const int cur = it % STG;
        if (it + STG - 1 < nIter) issue(it + STG - 1);
        cp_commit();

        const uint32_t aB = aBase + cur * ASZB;
        const uint32_t bB = bBase + cur * BSZB;
#pragma unroll
        for (int kk = 0; kk < 32; kk += 16) {
            uint32_t a[4][4], b[4][2];
#pragma unroll
            for (int mt = 0; mt < 4; mt++) {
                uint32_t off = ((aLaneRow + mt * 16) * ASTR + kk + aLaneK) * 2;
                ldsm_x4(aB + off, a[mt][0], a[mt][1], a[mt][2], a[mt][3]);
            }
#pragma unroll
            for (int nt = 0; nt < 4; nt++) {
                uint32_t off = ((kk + bLaneK) * BSTR + bLaneCol + nt * 8) * 2;
                ldsm_x2t(bB + off, b[nt][0], b[nt][1]);
            }
#pragma unroll
            for (int mt = 0; mt < 4; mt++)
#pragma unroll
                for (int nt = 0; nt < 4; nt++)
                    mma_bf16(acc[mt][nt], a[mt], b[nt]);
        }
        cp_wait<STG - 2>();
        __syncthreads();
    }

    const int rBase = by * 128 + wm * 64 + (lane >> 2);
    const int cBase = cColBase + wn * 32 + (lane & 3) * 2;
#pragma unroll
    for (int mt = 0; mt < 4; mt++)
#pragma unroll
        for (int nt = 0; nt < 4; nt++) {
            int r0 = rBase + mt * 16;
            int c0 = cBase + nt * 8;
            if (c0 < N) {
                *reinterpret_cast<float2*>(C + (size_t)r0 * N + c0) =
                    make_float2(acc[mt][nt][0], acc[mt][nt][1]);
                *reinterpret_cast<float2*>(C + (size_t)(r0 + 8) * N + c0) =
                    make_float2(acc[mt][nt][2], acc[mt][nt][3]);
            }
        }
}

// ---------------- RoPE ----------------
__global__ void rope_kernel(const float* __restrict__ cosp, const float* __restrict__ sinp) {
    int t = blockIdx.x;
    float* row = g_qkvw + (size_t)t * OUTD;
    for (int i = threadIdx.x; i < (H_ + HKV) * 32; i += blockDim.x) {
        int head = i >> 5, dp = i & 31;
        float* base = (head < H_) ? (row + OQ + head * DQK)
                                  : (row + OK_ + (head - H_) * DQK);
        float x1 = base[dp], x2 = base[dp + 32];
        float c1 = cosp[t * DQK + dp],      s1 = sinp[t * DQK + dp];
        float c2 = cosp[t * DQK + dp + 32], s2 = sinp[t * DQK + dp + 32];
        base[dp]      = x1 * c1 - x2 * s1;
        base[dp + 32] = x2 * c2 + x1 * s2;
    }
}

// ---------------- mean pool ----------------
__global__ void pool_kernel() {
    int idx = blockIdx.x * blockDim.x + threadIdx.x;
    if (idx >= NB * G_ * DQK) return;
    int nb = idx / (G_ * DQK);
    int g  = (idx / DQK) % G_;
    int d  = idx % DQK;
    float sk = 0.f, sv = 0.f;
    for (int i = 0; i < BLK; i++) {
        const float* r = g_qkvw + (size_t)(nb * BLK + i) * OUTD;
        sk += r[OK_ + g * DQK + d];
        sv += r[OV  + g * DV  + d];
    }
    g_kcmp[idx] = sk * (1.f / BLK);
    g_vcmp[idx] = sv * (1.f / BLK);
}

// ---------------- compressed branch + top-k (unchanged) ----------------
__global__ void cmp_kernel2() {
    extern __shared__ float sm[];
    float* kbuf = sm;
    float* p    = sm + 4096;
    float* imp  = p + TT * 16 * 64;
    const int t0 = blockIdx.x * TT;
    const int g  = blockIdx.y;
    const int tid = threadIdx.x;

    for (int i = tid; i < NB * DQK / 4; i += 256) {
        int n = i >> 4, d4 = (i & 15) << 2;
        *reinterpret_cast<float4*>(&kbuf[n * 64 + d4]) =
            *reinterpret_cast<const float4*>(&g_kcmp[(n * G_ + g) * DQK + d4]);
    }
    __syncthreads();

    const int row = tid >> 1;
    const int tt = row >> 4, hh = row & 15;
    const int t = t0 + tt;
    const int half = tid & 1;
    {
        float4 q[16];
        const float4* qp = reinterpret_cast<const float4*>(
            g_qkvw + (size_t)t * OUTD + OQ + (g * HG + hh) * DQK);
#pragma unroll
        for (int i = 0; i < 16; i++) q[i] = qp[i];
        const int nvis = (t + 1) >> 5;
        float* prow = p + row * 64;
        for (int n = half * 32; n < half * 32 + 32; n++) {
            float s = NEGI;
            if (n < nvis) {
                float a = 0.f;
#pragma unroll
                for (int i = 0; i < 16; i++) {
                    float4 kv = *reinterpret_cast<float4*>(&kbuf[n * 64 + i * 4]);
                    a += q[i].x * kv.x + q[i].y * kv.y + q[i].z * kv.z + q[i].w * kv.w;
                }
                s = a * SCALE;
            }
            prow[n] = s;
        }
    }
    __syncthreads();

    for (int i = tid; i < NB * DV / 4; i += 256) {
        int n = i >> 4, d4 = (i & 15) << 2;
        *reinterpret_cast<float4*>(&kbuf[n * 64 + d4]) =
            *reinterpret_cast<const float4*>(&g_vcmp[(n * G_ + g) * DV + d4]);
    }
    if (tid < 128) {
        float* pr = p + tid * 64;
        int tloc = t0 + (tid >> 4);
        int nv = (tloc + 1) >> 5;
        if (nv == 0) {
            for (int n = 0; n < 64; n++) pr[n] = 0.f;
        } else {
            float m = NEGI;
            for (int n = 0; n < 64; n++) m = fmaxf(m, pr[n]);
            float s = 0.f;
            for (int n = 0; n < 64; n++) { float e = __expf(pr[n] - m); pr[n] = e; s += e; }
            float inv = 1.f / s;
            for (int n = 0; n < 64; n++) pr[n] *= inv;
        }
    }
    __syncthreads();

    for (int i = tid; i < TT * NB; i += 256) {
        int tti = i >> 6, n = i & 63;
        int tloc = t0 + tti, cur = tloc >> 5;
        float v;
        if (n > cur) v = NEGI;
        else {
            v = 0.f;
            for (int h2 = 0; h2 < 16; h2++) v += p[(tti * 16 + h2) * 64 + n];
            if (n == 0)   v += 1e4f;
            if (n == cur) v += 1e4f;
        }
        imp[i] = v;
    }
    __syncthreads();

    {
        int wid = tid >> 5, lane = tid & 31;
        if (wid < TT) {
            float v0 = imp[wid * 64 + lane];
            float v1 = imp[wid * 64 + 32 + lane];
            int* outp = g_selidx + ((t0 + wid) * G_ + g) * NSEL;
            for (int j = 0; j < NSEL; j++) {
                float bv = v0; int bi = lane;
                if (v1 > bv) { bv = v1; bi = lane + 32; }
#pragma unroll
                for (int off = 16; off; off >>= 1) {
                    float ov = __shfl_xor_sync(0xffffffffu, bv, off);
                    int   oi = __shfl_xor_sync(0xffffffffu, bi, off);
                    if (ov > bv || (ov == bv && oi < bi)) { bv = ov; bi = oi; }
                }
                if (lane == 0) outp[j] = bi;
                if (bi == lane)      v0 = -2e30f;
                if (bi == lane + 32) v1 = -2e30f;
            }
        }
    }

    {
        const int nv = (t + 1) >> 5;
        float acc[32];
#pragma unroll
        for (int i = 0; i < 32; i++) acc[i] = 0.f;
        const float* pr = p + row * 64;
        for (int n = 0; n < nv; n++) {
            float w = pr[n];
            const float* vr = kbuf + n * 64 + half * 32;
#pragma unroll
            for (int i = 0; i < 8; i++) {
                float4 v4 = *reinterpret_cast<const float4*>(&vr[i * 4]);
                acc[i * 4 + 0] += w * v4.x; acc[i * 4 + 1] += w * v4.y;
                acc[i * 4 + 2] += w * v4.z; acc[i * 4 + 3] += w * v4.w;
            }
        }
        float* op = g_ocmp + ((size_t)t * H_ + g * HG + hh) * DV + half * 32;
#pragma unroll
        for (int i = 0; i < 8; i++)
            *reinterpret_cast<float4*>(&op[i * 4]) =
                make_float4(acc[i * 4], acc[i * 4 + 1], acc[i * 4 + 2], acc[i * 4 + 3]);
    }
}

// ---------------- tensor-core attention branch (sel / win) ----------------
// grid (T, G), 256 threads (8 warps). S = Q@K^T and O = P@V via bf16x3 mma.
template <bool IS_SEL>
__global__ void attn_mma_kernel() {
    extern __shared__ char smraw[];
    const uint32_t smb = smem_u32(smraw);
    float* p = reinterpret_cast<float*>(smraw + P_OFF);
    int* sidx = reinterpret_cast<int*>(smraw + SIDX_OFF);

    const int t = blockIdx.x, g = blockIdx.y, tid = threadIdx.x;
    const int lane = tid & 31, wid = tid >> 5;
    const int w0 = t - (WINSZ - 1);

    if (IS_SEL && tid < NSEL) sidx[tid] = g_selidx[(t * G_ + g) * NSEL + tid];

    // stage Q hi/lo: 16 rows x 8 uint4 x 2 bufs = 256 iterations
    {
        int i = tid;
        int buf = i >> 7, rest = i & 127, r = rest >> 3, c = rest & 7;
        const __nv_bfloat16* src = (buf ? g_ql : g_qh) + ((size_t)t * H_ + g * HG + r) * 64 + c * 8;
        *reinterpret_cast<uint4*>(smraw + Q_OFF + buf * QL_OFF + (r * 72 + c * 8) * 2) =
            *reinterpret_cast<const uint4*>(src);
    }
    __syncthreads();

    // stage K^T hi/lo: [64 d][264 cols], 64*32 groups * 2 bufs
    for (int i = tid; i < 4096; i += 256) {
        const int buf = i >> 11, rest = i & 2047;
        const int d = rest >> 5, c8 = rest & 31;
        const __nv_bfloat16* sp = (buf ? g_klT : g_khT) + (size_t)(g * 64 + d) * TPAD;
        char* dst = smraw + buf * KT_LO_OFF + (d * 264 + c8 * 8) * 2;
        uint4 val;
        if (IS_SEL) {
            int tb = sidx[c8 >> 2] * BLK + (c8 & 3) * 8;
            val = *reinterpret_cast<const uint4*>(sp + tb);
        } else {
            int tb = w0 + c8 * 8;
            if (tb >= 0) {
                int dl = tb & 7;
                const uint32_t* s32 = reinterpret_cast<const uint32_t*>(sp + (tb - dl));
                if (dl == 0) {
                    val = *reinterpret_cast<const uint4*>(s32);
                } else {
                    uint32_t s0[8];
#pragma unroll
                    for (int j = 0; j < 8; j++) s0[j] = s32[j];
                    int qo = dl >> 1;
                    if (dl & 1) {
                        val.x = __funnelshift_r(s0[qo],     s0[qo + 1], 16);
                        val.y = __funnelshift_r(s0[qo + 1], s0[qo + 2], 16);
                        val.z = __funnelshift_r(s0[qo + 2], s0[qo + 3], 16);
                        val.w = __funnelshift_r(s0[qo + 3], s0[qo + 4], 16);
                    } else {
                        val.x = s0[qo]; val.y = s0[qo + 1]; val.z = s0[qo + 2]; val.w = s0[qo + 3];
                    }
                }
            } else {
                const unsigned short* su = reinterpret_cast<const unsigned short*>(sp);
                unsigned short tmp[8];
#pragma unroll
                for (int j = 0; j < 8; j++) { int ti = tb + j; tmp[j] = su[ti < 0 ? 0 : ti]; }
                val.x = tmp[0] | ((uint32_t)tmp[1] << 16);
                val.y = tmp[2] | ((uint32_t)tmp[3] << 16);
                val.z = tmp[4] | ((uint32_t)tmp[5] << 16);
                val.w = tmp[6] | ((uint32_t)tmp[7] << 16);
            }
        }
        *reinterpret_cast<uint4*>(dst) = val;
    }
    __syncthreads();

    // Q a-frags: 2 bufs x 4 k-steps
    uint32_t aq[2][4][4];
#pragma unroll
    for (int kk = 0; kk < 4; kk++) {
        uint32_t qaddr = smb + Q_OFF + ((lane & 15) * 72 + kk * 16 + ((lane >> 4) << 3)) * 2;
        ldsm_x4(qaddr, aq[0][kk][0], aq[0][kk][1], aq[0][kk][2], aq[0][kk][3]);
        ldsm_x4(qaddr + QL_OFF, aq[1][kk][0], aq[1][kk][1], aq[1][kk][2], aq[1][kk][3]);
    }

    // score mma: warp owns n-cols [wid*32, wid*32+32)
    float sc[4][4];
#pragma unroll
    for (int nt = 0; nt < 4; nt++)
#pragma unroll
        for (int r = 0; r < 4; r++) sc[nt][r] = 0.f;
#pragma unroll
    for (int kk = 0; kk < 4; kk++) {
#pragma unroll
        for (int nt = 0; nt < 4; nt++) {
            uint32_t baddr = smb + ((kk * 16 + (lane & 15)) * 264 + wid * 32 + nt * 8) * 2;
            uint32_t bh[2], bl[2];
            ldsm_x2t(baddr, bh[0], bh[1]);
            ldsm_x2t(baddr + KT_LO_OFF, bl[0], bl[1]);
            mma_bf16(sc[nt], aq[0][kk], bh);
            mma_bf16(sc[nt], aq[1][kk], bh);
            mma_bf16(sc[nt], aq[0][kk], bl);
        }
    }

    // write masked, scaled scores to p
    {
        const int srow = lane >> 2;
#pragma unroll
        for (int nt = 0; nt < 4; nt++) {
            int c0 = wid * 32 + nt * 8 + (lane & 3) * 2;
            bool v0, v1;
            if (IS_SEL) {
                v0 = sidx[c0 >> 5] * BLK + (c0 & 31) <= t;
                v1 = sidx[(c0 + 1) >> 5] * BLK + ((c0 + 1) & 31) <= t;
            } else {
                v0 = (w0 + c0) >= 0;
                v1 = (w0 + c0 + 1) >= 0;
            }
            p[srow * 256 + c0]           = v0 ? sc[nt][0] * SCALE : NEGI;
            p[srow * 256 + c0 + 1]       = v1 ? sc[nt][1] * SCALE : NEGI;
            p[(srow + 8) * 256 + c0]     = v0 ? sc[nt][2] * SCALE : NEGI;
            p[(srow + 8) * 256 + c0 + 1] = v1 ? sc[nt][3] * SCALE : NEGI;
        }
    }
    __syncthreads();

    // stage V hi/lo (overwrites K^T region): [256 r][72] rows
    for (int i = tid; i < 4096; i += 256) {
        const int buf = i >> 11, rest = i & 2047;
        const int s = rest >> 3, c = rest & 7;
        int trow;
        if (IS_SEL) trow = sidx[s >> 5] * BLK + (s & 31);
        else { trow = w0 + s; if (trow < 0) trow = 0; }
        const __nv_bfloat16* src = (buf ? g_vl : g_vh) + ((size_t)trow * G_ + g) * 64 + c * 8;
        *reinterpret_cast<uint4*>(smraw + buf * V_LO_OFF + (s * 72 + c * 8) * 2) =
            *reinterpret_cast<const uint4*>(src);
    }

    // softmax over 256 (warp per 2 rows) - overlaps with V staging loads
    {
#pragma unroll
        for (int rr = 0; rr < 2; rr++) {
            float* pr = p + (wid * 2 + rr) * 256;
            float v[8];
            float m = NEGI;
#pragma unroll
            for (int i = 0; i < 8; i++) { v[i] = pr[i * 32 + lane]; m = fmaxf(m, v[i]); }
#pragma unroll
            for (int off = 16; off; off >>= 1) m = fmaxf(m, __shfl_xor_sync(0xffffffffu, m, off));
            float s = 0.f;
#pragma unroll
            for (int i = 0; i < 8; i++) { v[i] = __expf(v[i] - m); s += v[i]; }
#pragma unroll
            for (int off = 16; off; off >>= 1) s += __shfl_xor_sync(0xffffffffu, s, off);
            float inv = 1.f / s;
#pragma unroll
            for (int i = 0; i < 8; i++) pr[i * 32 + lane] = v[i] * inv;
        }
    }
    __syncthreads();

    // convert P -> bf16 hi/lo in place (thread owns column tid across 16 rows)
    {
        float pv[16];
#pragma unroll
        for (int j = 0; j < 16; j++) pv[j] = p[j * 256 + tid];
        __syncthreads();
#pragma unroll
        for (int j = 0; j < 16; j++) {
            __nv_bfloat16 h = __float2bfloat16(pv[j]);
            __nv_bfloat16 l = __float2bfloat16(pv[j] - __bfloat162float(h));
            *reinterpret_cast<__nv_bfloat16*>(smraw + P_OFF + (j * 264 + tid) * 2) = h;
            *reinterpret_cast<__nv_bfloat16*>(smraw + P_OFF + PSM_LO + (j * 264 + tid) * 2) = l;
        }
    }
    __syncthreads();

    // pV mma: warp owns d-cols [wid*8, wid*8+8)
    float oc[4] = {0.f, 0.f, 0.f, 0.f};
#pragma unroll 4
    for (int kk = 0; kk < 16; kk++) {
        uint32_t pa = smb + P_OFF + ((lane & 15) * 264 + kk * 16 + ((lane >> 4) << 3)) * 2;
        uint32_t ah[4], al[4], bh[2], bl[2];
        ldsm_x4(pa, ah[0], ah[1], ah[2], ah[3]);
        ldsm_x4(pa + PSM_LO, al[0], al[1], al[2], al[3]);
        uint32_t va = smb + ((kk * 16 + (lane & 15)) * 72 + wid * 8) * 2;
        ldsm_x2t(va, bh[0], bh[1]);
        ldsm_x2t(va + V_LO_OFF, bl[0], bl[1]);
        mma_bf16(oc, ah, bh);
        mma_bf16(oc, al, bh);
        mma_bf16(oc, ah, bl);
    }

    float* dst = (IS_SEL ? g_osel : g_owin) + ((size_t)t * H_ + g * HG) * DV;
    const int orow = lane >> 2, ocol = wid * 8 + (lane & 3) * 2;
    *reinterpret_cast<float2*>(dst + orow * 64 + ocol)       = make_float2(oc[0], oc[1]);
    *reinterpret_cast<float2*>(dst + (orow + 8) * 64 + ocol) = make_float2(oc[2], oc[3]);
}

// ---------------- gated combine + bf16 split ----------------
__global__ void combine_split_kernel() {
    int i = blockIdx.x * blockDim.x + threadIdx.x;
    if (i >= T_ * H_ * DV / 2) return;
    int e = 2 * i;
    int h = (e >> 6) & 31;
    int t = e >> 11;
    const float* wrow = g_qkvw + (size_t)t * OUTD + OW + h * 3;
    float g0 = 1.f / (1.f + __expf(-wrow[0]));
    float g1 = 1.f / (1.f + __expf(-wrow[1]));
    float g2 = 1.f / (1.f + __expf(-wrow[2]));
    float o0 = g0 * g_ocmp[e]     + g1 * g_osel[e]     + g2 * g_owin[e];
    float o1 = g0 * g_ocmp[e + 1] + g1 * g_osel[e + 1] + g2 * g_owin[e + 1];
    uint32_t hi, lo;
    split2(o0, o1, hi, lo);
    reinterpret_cast<uint32_t*>(g_och)[i] = hi;
    reinterpret_cast<uint32_t*>(g_ocl)[i] = lo;
}

// ---------------- launch ----------------
extern "C" void kernel_launch(void* const* d_in, const int* in_sizes, int n_in,
                              void* d_out, int out_size) {
    const float* x    = (const float*)d_in[0];
    const float* cosp = (const float*)d_in[1];
    const float* sinp = (const float*)d_in[2];
    const float* wqkv = (const float*)d_in[3];
    const float* ow   = (const float*)d_in[4];
    float* out = (float*)d_out;

    float* qkvw_p;
    cudaGetSymbolAddress((void**)&qkvw_p, g_qkvw);
    __nv_bfloat16 *xh, *xl, *wh, *wl, *owh, *owl, *och, *ocl;
    cudaGetSymbolAddress((void**)&xh, g_xh);   cudaGetSymbolAddress((void**)&xl, g_xl);
    cudaGetSymbolAddress((void**)&wh, g_wh);   cudaGetSymbolAddress((void**)&wl, g_wl);
    cudaGetSymbolAddress((void**)&owh, g_owh); cudaGetSymbolAddress((void**)&owl, g_owl);
    cudaGetSymbolAddress((void**)&och, g_och); cudaGetSymbolAddress((void**)&ocl, g_ocl);

    const int CMP_SMEM = (64 * 64 + TT * 16 * 64 + TT * 64) * 4;
    cudaFuncSetAttribute((const void*)gemm_k3, cudaFuncAttributeMaxDynamicSharedMemorySize, GEMM_SMEM);
    cudaFuncSetAttribute((const void*)cmp_kernel2, cudaFuncAttributeMaxDynamicSharedMemorySize, CMP_SMEM);
    cudaFuncSetAttribute((const void*)attn_mma_kernel<true>,  cudaFuncAttributeMaxDynamicSharedMemorySize, ATT_SMEM);
    cudaFuncSetAttribute((const void*)attn_mma_kernel<false>, cudaFuncAttributeMaxDynamicSharedMemorySize, ATT_SMEM);

    split_kernel<<<(T_ * HID / 2 + 255) / 256, 256>>>(x, xh, xl, T_ * HID / 2);
    split_kernel<<<(HID * OUTD / 2 + 255) / 256, 256>>>(wqkv, wh, wl, HID * OUTD / 2);
    split_kernel<<<(H_ * DV * HID / 2 + 255) / 256, 256>>>(ow, owh, owl, H_ * DV * HID / 2);

    dim3 g1((OUTD + 127) / 128, T_ / 128);
    gemm_k3<<<g1, 256, GEMM_SMEM>>>(xh, xl, wh, wl, qkvw_p, T_, OUTD, HID);

    rope_kernel<<<T_, 256>>>(cosp, sinp);
    pool_kernel<<<(NB * G_ * DQK + 255) / 256, 256>>>();
    split_qkv_kernel<<<T_, 256>>>();

    dim3 gc(T_ / TT, G_);
    cmp_kernel2<<<gc, 256, CMP_SMEM>>>();

    dim3 gt(T_, G_);
    attn_mma_kernel<true><<<gt, 256, ATT_SMEM>>>();
    attn_mma_kernel<false><<<gt, 256, ATT_SMEM>>>();

    combine_split_kernel<<<(T_ * H_ * DV / 2 + 255) / 256, 256>>>();

    dim3 g2(HID / 128, T_ / 128);
    gemm_k3<<<g2, 256, GEMM_SMEM>>>(och, ocl, owh, owl, out, T_, HID, HID);
}